// round 1
// baseline (speedup 1.0000x reference)
#include <cuda_runtime.h>
#include <math.h>

// ---------------------------------------------------------------------------
// MultiLevelSimCLR: instance-level + patch-level InfoNCE, fused into a scalar.
//
// Inputs (metadata order):
//   0: v1_ins   float32 [8192, 128]
//   1: v2_ins   float32 [8192, 128]
//   2: v1_patch float32 [256, 128, 256]
//   3: v2_patch float32 [256, 128, 256]
//   4: v1_counts int32  [256, 256]
//   5: v2_counts int32  [256, 256]
// Output: float32 [1]
// ---------------------------------------------------------------------------

#define B_INS    8192
#define N_INS    16384          // 2*B
#define D        128
#define BP       256
#define P        256
#define N_PAT    512            // 2*P
#define INV_TEMP 10.0f
#define NEGV     (-1e30f)

// Device scratch (static allocation -- allowed)
__device__ float g_embsT[D * N_INS];        // normalized instance embs, [k][j], 8 MB
__device__ float g_rins[N_INS];             // instance inverse norms
__device__ float g_rp[BP * N_PAT];          // patch inverse norms, [b][j]
__device__ float g_pins[256];               // per-block instance loss partials
__device__ float g_pp[2048];                // per-block patch loss partials

#define SMEM_FLOATS (128 * 64 * 2 + 64)
#define SMEM_BYTES  (SMEM_FLOATS * 4)

// ---------------------------------------------------------------------------
// Kernel 1: instance inverse norms (one warp per row)
// ---------------------------------------------------------------------------
__global__ void k_ins_rnorm(const float* __restrict__ v1, const float* __restrict__ v2) {
    int gw   = (blockIdx.x * blockDim.x + threadIdx.x) >> 5;
    int lane = threadIdx.x & 31;
    if (gw >= N_INS) return;
    const float* src = (gw < B_INS) ? (v1 + (size_t)gw * D) : (v2 + (size_t)(gw - B_INS) * D);
    float4 x = ((const float4*)src)[lane];
    float ss = x.x * x.x + x.y * x.y + x.z * x.z + x.w * x.w;
#pragma unroll
    for (int off = 16; off; off >>= 1) ss += __shfl_xor_sync(0xffffffffu, ss, off);
    if (lane == 0) g_rins[gw] = 1.0f / fmaxf(sqrtf(ss), 1e-12f);
}

// ---------------------------------------------------------------------------
// Kernel 2: normalize + transpose instance embs into g_embsT[k][j]
// grid (512, 4), block (32, 8)
// ---------------------------------------------------------------------------
__global__ void k_ins_transpose(const float* __restrict__ v1, const float* __restrict__ v2) {
    __shared__ float t[32][33];
    int j0 = blockIdx.x * 32;
    int k0 = blockIdx.y * 32;
    int tx = threadIdx.x, ty = threadIdx.y;
#pragma unroll
    for (int it = 0; it < 4; it++) {
        int j = j0 + ty + it * 8;
        const float* src = (j < B_INS) ? (v1 + (size_t)j * D) : (v2 + (size_t)(j - B_INS) * D);
        t[ty + it * 8][tx] = src[k0 + tx] * g_rins[j];
    }
    __syncthreads();
#pragma unroll
    for (int it = 0; it < 4; it++) {
        int k = k0 + ty + it * 8;
        g_embsT[(size_t)k * N_INS + j0 + tx] = t[tx][ty + it * 8];
    }
}

// ---------------------------------------------------------------------------
// Kernel 3: patch inverse norms. One thread per (b, j).
// ---------------------------------------------------------------------------
__global__ void k_patch_rnorm(const float* __restrict__ v1p, const float* __restrict__ v2p) {
    int t = blockIdx.x * blockDim.x + threadIdx.x;
    if (t >= BP * N_PAT) return;
    int b = t >> 9;
    int j = t & 511;
    const float* src = ((j < P) ? v1p : v2p) + (size_t)b * D * P + (j & 255);
    float ss = 0.0f;
#pragma unroll 8
    for (int k = 0; k < D; k++) {
        float x = src[(size_t)k * P];
        ss += x * x;
    }
    g_rp[t] = 1.0f / fmaxf(sqrtf(ss), 1e-12f);
}

// ---------------------------------------------------------------------------
// Shared micro-kernel helpers
// ---------------------------------------------------------------------------
__device__ __forceinline__ float redmax16(float v) {
#pragma unroll
    for (int off = 8; off; off >>= 1) v = fmaxf(v, __shfl_xor_sync(0xffffffffu, v, off));
    return v;
}
__device__ __forceinline__ float redsum16(float v) {
#pragma unroll
    for (int off = 8; off; off >>= 1) v += __shfl_xor_sync(0xffffffffu, v, off);
    return v;
}

#define MMA_4x4(a, b, acc)                                            \
    acc[0][0] += a.x * b.x; acc[0][1] += a.x * b.y;                   \
    acc[0][2] += a.x * b.z; acc[0][3] += a.x * b.w;                   \
    acc[1][0] += a.y * b.x; acc[1][1] += a.y * b.y;                   \
    acc[1][2] += a.y * b.z; acc[1][3] += a.y * b.w;                   \
    acc[2][0] += a.z * b.x; acc[2][1] += a.z * b.y;                   \
    acc[2][2] += a.z * b.z; acc[2][3] += a.z * b.w;                   \
    acc[3][0] += a.w * b.x; acc[3][1] += a.w * b.y;                   \
    acc[3][2] += a.w * b.z; acc[3][3] += a.w * b.w;

// ---------------------------------------------------------------------------
// Kernel 4: instance CE. grid 256 blocks (64 rows each), 256 threads.
// Online logsumexp over 256 column tiles of 64.
// ---------------------------------------------------------------------------
__global__ void k_ins_ce() {
    extern __shared__ float sm[];
    float* As  = sm;                // [128][64] k-major
    float* Bs  = sm + 8192;
    float* red = sm + 16384;

    int tid  = threadIdx.x;
    int tx   = tid & 15;
    int ty   = tid >> 4;
    int row0 = blockIdx.x * 64;

    const float4* E4 = (const float4*)g_embsT;   // row k: 4096 float4

    // Load A tile once (rows of this block)
#pragma unroll
    for (int it = 0; it < 8; it++) {
        int i = tid + it * 256;
        int k = i >> 4;
        int m = i & 15;
        ((float4*)As)[k * 16 + m] = E4[(size_t)k * 4096 + (row0 >> 2) + m];
    }

    float M[4], S[4], pos[4];
#pragma unroll
    for (int i = 0; i < 4; i++) { M[i] = -INFINITY; S[i] = 0.0f; pos[i] = 0.0f; }

    for (int ct = 0; ct < 256; ct++) {
        int col0 = ct * 64;
        __syncthreads();
#pragma unroll
        for (int it = 0; it < 8; it++) {
            int i = tid + it * 256;
            int k = i >> 4;
            int m = i & 15;
            ((float4*)Bs)[k * 16 + m] = E4[(size_t)k * 4096 + (col0 >> 2) + m];
        }
        __syncthreads();

        float acc[4][4] = {{0.f,0.f,0.f,0.f},{0.f,0.f,0.f,0.f},{0.f,0.f,0.f,0.f},{0.f,0.f,0.f,0.f}};
#pragma unroll 8
        for (int k = 0; k < 128; k++) {
            float4 a = *(const float4*)(As + k * 64 + ty * 4);
            float4 b = *(const float4*)(Bs + k * 64 + tx * 4);
            MMA_4x4(a, b, acc);
        }

#pragma unroll
        for (int i = 0; i < 4; i++) {
            int r   = row0 + ty * 4 + i;
            int lbl = r ^ B_INS;
            float vv[4];
            float vmax = -INFINITY;
#pragma unroll
            for (int j = 0; j < 4; j++) {
                int c = col0 + tx * 4 + j;
                float v = acc[i][j] * INV_TEMP;
                if (c == lbl) pos[i] += v;
                if (c == r)   v = NEGV;
                vv[j] = v;
                vmax = fmaxf(vmax, v);
            }
            float mt = redmax16(vmax);
            float st = 0.0f;
#pragma unroll
            for (int j = 0; j < 4; j++) st += __expf(vv[j] - mt);
            st = redsum16(st);
            float mn = fmaxf(M[i], mt);
            S[i] = S[i] * __expf(M[i] - mn) + st * __expf(mt - mn);
            M[i] = mn;
        }
    }

#pragma unroll
    for (int i = 0; i < 4; i++) {
        float p = redsum16(pos[i]);
        if (tx == 0) red[ty * 4 + i] = (M[i] + logf(S[i])) - p;
    }
    __syncthreads();
    if (tid == 0) {
        float s = 0.0f;
        for (int i = 0; i < 64; i++) s += red[i];
        g_pins[blockIdx.x] = s;
    }
}

// ---------------------------------------------------------------------------
// Kernel 5: patch CE. grid (8 row-tiles, 256 batches), 256 threads.
// Patch data is already k-major in memory ([b][d][p]); scale by rnorm at load.
// ---------------------------------------------------------------------------
__global__ void k_patch_ce(const float* __restrict__ v1p, const float* __restrict__ v2p,
                           const int* __restrict__ c1,  const int* __restrict__ c2) {
    extern __shared__ float sm[];
    float* As  = sm;
    float* Bs  = sm + 8192;
    float* red = sm + 16384;

    int tid  = threadIdx.x;
    int tx   = tid & 15;
    int ty   = tid >> 4;
    int b    = blockIdx.y;
    int row0 = blockIdx.x * 64;

    // Load A tile (columns row0..row0+63 of E[b], scaled)
    {
        const float* srcA = ((row0 < P) ? v1p : v2p) + (size_t)b * D * P + (row0 & 255);
        const float4* rn4 = (const float4*)(g_rp + b * N_PAT + row0);
#pragma unroll
        for (int it = 0; it < 8; it++) {
            int i = tid + it * 256;
            int k = i >> 4;
            int m = i & 15;
            float4 v = ((const float4*)(srcA + (size_t)k * P))[m];
            float4 s = rn4[m];
            v.x *= s.x; v.y *= s.y; v.z *= s.z; v.w *= s.w;
            ((float4*)As)[k * 16 + m] = v;
        }
    }

    float M[4], S[4], pos[4];
#pragma unroll
    for (int i = 0; i < 4; i++) { M[i] = -INFINITY; S[i] = 0.0f; pos[i] = 0.0f; }

    for (int ct = 0; ct < 8; ct++) {
        int col0 = ct * 64;
        __syncthreads();
        {
            const float* srcB = ((col0 < P) ? v1p : v2p) + (size_t)b * D * P + (col0 & 255);
            const float4* rn4 = (const float4*)(g_rp + b * N_PAT + col0);
#pragma unroll
            for (int it = 0; it < 8; it++) {
                int i = tid + it * 256;
                int k = i >> 4;
                int m = i & 15;
                float4 v = ((const float4*)(srcB + (size_t)k * P))[m];
                float4 s = rn4[m];
                v.x *= s.x; v.y *= s.y; v.z *= s.z; v.w *= s.w;
                ((float4*)Bs)[k * 16 + m] = v;
            }
        }
        __syncthreads();

        float acc[4][4] = {{0.f,0.f,0.f,0.f},{0.f,0.f,0.f,0.f},{0.f,0.f,0.f,0.f},{0.f,0.f,0.f,0.f}};
#pragma unroll 8
        for (int k = 0; k < 128; k++) {
            float4 a = *(const float4*)(As + k * 64 + ty * 4);
            float4 b4 = *(const float4*)(Bs + k * 64 + tx * 4);
            MMA_4x4(a, b4, acc);
        }

#pragma unroll
        for (int i = 0; i < 4; i++) {
            int r   = row0 + ty * 4 + i;
            int lbl = r ^ P;
            float vv[4];
            float vmax = -INFINITY;
#pragma unroll
            for (int j = 0; j < 4; j++) {
                int c = col0 + tx * 4 + j;
                float v = acc[i][j] * INV_TEMP;
                if (c == lbl) pos[i] += v;
                if (c == r)   v = NEGV;
                vv[j] = v;
                vmax = fmaxf(vmax, v);
            }
            float mt = redmax16(vmax);
            float st = 0.0f;
#pragma unroll
            for (int j = 0; j < 4; j++) st += __expf(vv[j] - mt);
            st = redsum16(st);
            float mn = fmaxf(M[i], mt);
            S[i] = S[i] * __expf(M[i] - mn) + st * __expf(mt - mn);
            M[i] = mn;
        }
    }

#pragma unroll
    for (int i = 0; i < 4; i++) {
        float p = redsum16(pos[i]);
        if (tx == 0) {
            int r = row0 + ty * 4 + i;
            int cval = (r < P) ? c1[b * P + r] : c2[b * P + (r - P)];
            float loss = (M[i] + logf(S[i])) - p;
            red[ty * 4 + i] = (cval != 0) ? loss : 0.0f;
        }
    }
    __syncthreads();
    if (tid == 0) {
        float s = 0.0f;
        for (int i = 0; i < 64; i++) s += red[i];
        g_pp[b * 8 + blockIdx.x] = s;
    }
}

// ---------------------------------------------------------------------------
// Kernel 6: deterministic final reduction
// ---------------------------------------------------------------------------
__global__ void k_finalize(const int* __restrict__ c1, const int* __restrict__ c2,
                           float* __restrict__ out) {
    __shared__ float sred[256];
    __shared__ int   sint[256];
    int tid = threadIdx.x;

    float pins = g_pins[tid];
    float pp = 0.0f;
#pragma unroll
    for (int i = 0; i < 8; i++) pp += g_pp[tid + i * 256];
    int cnt = 0;
    for (int i = tid; i < BP * P; i += 256)
        cnt += (c1[i] != 0) + (c2[i] != 0);

    sred[tid] = pins;
    sint[tid] = cnt;
    __syncthreads();
    for (int s = 128; s; s >>= 1) {
        if (tid < s) { sred[tid] += sred[tid + s]; sint[tid] += sint[tid + s]; }
        __syncthreads();
    }
    float ins_sum = sred[0];
    int   nvalid  = sint[0];
    __syncthreads();

    sred[tid] = pp;
    __syncthreads();
    for (int s = 128; s; s >>= 1) {
        if (tid < s) sred[tid] += sred[tid + s];
        __syncthreads();
    }
    if (tid == 0)
        out[0] = ins_sum / (float)N_INS + sred[0] / (float)nvalid;
}

// ---------------------------------------------------------------------------
extern "C" void kernel_launch(void* const* d_in, const int* in_sizes, int n_in,
                              void* d_out, int out_size) {
    const float* v1  = (const float*)d_in[0];
    const float* v2  = (const float*)d_in[1];
    const float* v1p = (const float*)d_in[2];
    const float* v2p = (const float*)d_in[3];
    const int*   c1  = (const int*)d_in[4];
    const int*   c2  = (const int*)d_in[5];
    float* out = (float*)d_out;

    cudaFuncSetAttribute(k_ins_ce,   cudaFuncAttributeMaxDynamicSharedMemorySize, SMEM_BYTES);
    cudaFuncSetAttribute(k_patch_ce, cudaFuncAttributeMaxDynamicSharedMemorySize, SMEM_BYTES);

    k_ins_rnorm<<<(N_INS * 32 + 255) / 256, 256>>>(v1, v2);
    k_ins_transpose<<<dim3(N_INS / 32, D / 32), dim3(32, 8)>>>(v1, v2);
    k_patch_rnorm<<<(BP * N_PAT + 255) / 256, 256>>>(v1p, v2p);
    k_ins_ce<<<N_INS / 64, 256, SMEM_BYTES>>>();
    k_patch_ce<<<dim3(N_PAT / 64, BP), 256, SMEM_BYTES>>>(v1p, v2p, c1, c2);
    k_finalize<<<1, 256>>>(c1, c2, out);
}

// round 3
// speedup vs baseline: 5.2466x; 5.2466x over previous
#include <cuda_runtime.h>
#include <cuda_bf16.h>
#include <cstdint>
#include <math.h>

// ---------------------------------------------------------------------------
// MultiLevelSimCLR via mma.sync.m16n8k16 bf16 (plain sm_80+ PTX; no tcgen05).
// Inputs: v1_ins f32[8192,128], v2_ins f32[8192,128],
//         v1_patch f32[256,128,256], v2_patch f32[256,128,256],
//         v1_counts i32[256,256], v2_counts i32[256,256]  -> out f32[1]
// ---------------------------------------------------------------------------

#define B_INS   8192
#define N_INS   16384
#define DDIM    128
#define NPROW   131072              // 256 batches * 512 rows
#define L2E10   14.4269504088896340f
#define STR     136                 // smem row stride in bf16 elems (conflict-free)

// ---- static device scratch ----
__device__ __align__(16) uint32_t g_I[N_INS * 64];   // normalized bf16 instance embs [r][128]
__device__ __align__(16) uint32_t g_P[NPROW * 64];   // normalized bf16 patch embs    [b*512+j][128]
__device__ float g_Sins[N_INS];
__device__ float g_Spat[NPROW];
__device__ float g_fin1[512];
__device__ float g_fin2[1024];

__device__ __forceinline__ float ex2f(float x) {
    float y; asm("ex2.approx.f32 %0, %1;" : "=f"(y) : "f"(x)); return y;
}

__device__ __forceinline__ void mma16816(float* c, const uint32_t* a, const uint32_t* b) {
    asm volatile(
        "mma.sync.aligned.m16n8k16.row.col.f32.bf16.bf16.f32 "
        "{%0,%1,%2,%3}, {%4,%5,%6,%7}, {%8,%9}, {%0,%1,%2,%3};"
        : "+f"(c[0]), "+f"(c[1]), "+f"(c[2]), "+f"(c[3])
        : "r"(a[0]), "r"(a[1]), "r"(a[2]), "r"(a[3]), "r"(b[0]), "r"(b[1]));
}

// ---------------------------------------------------------------------------
// Prep: normalize + bf16-convert instance embeddings (row-major out)
// ---------------------------------------------------------------------------
__global__ void prep_ins(const float* __restrict__ v1, const float* __restrict__ v2) {
    int lane = threadIdx.x & 31;
    int gw = (blockIdx.x * blockDim.x + threadIdx.x) >> 5;
    for (int r = gw; r < N_INS; r += 4096) {
        const float* src = (r < B_INS) ? v1 + (size_t)r * DDIM : v2 + (size_t)(r - B_INS) * DDIM;
        float4 x = ((const float4*)src)[lane];
        float ss = x.x * x.x + x.y * x.y + x.z * x.z + x.w * x.w;
#pragma unroll
        for (int o = 16; o; o >>= 1) ss += __shfl_xor_sync(~0u, ss, o);
        float ri = 1.0f / fmaxf(sqrtf(ss), 1e-12f);
        __nv_bfloat162 p0 = __floats2bfloat162_rn(x.x * ri, x.y * ri);
        __nv_bfloat162 p1 = __floats2bfloat162_rn(x.z * ri, x.w * ri);
        ((uint2*)g_I)[(size_t)r * 32 + lane] = make_uint2(*(uint32_t*)&p0, *(uint32_t*)&p1);
    }
}

// ---------------------------------------------------------------------------
// Prep: patch embeddings. Source [b][k][j]; transpose 32-j tiles through SMEM.
// ---------------------------------------------------------------------------
__global__ void prep_patch(const float* __restrict__ v1p, const float* __restrict__ v2p) {
    __shared__ float sb[2][32][129];
    int tid = threadIdx.x, lane = tid & 31, wid = tid >> 5;
    int j0 = blockIdx.x * 32;
    int b = blockIdx.y;
    const float* srcs[2] = { v1p + (size_t)b * DDIM * 256, v2p + (size_t)b * DDIM * 256 };
#pragma unroll
    for (int s = 0; s < 2; s++) {
        const float* src = srcs[s];
        for (int i = 0; i < 16; i++) {
            int idx = tid + i * 256;
            int k = idx >> 5, jj = idx & 31;
            sb[s][jj][k] = src[(size_t)k * 256 + j0 + jj];
        }
    }
    __syncthreads();
    for (int t = 0; t < 8; t++) {
        int rr = wid * 8 + t;
        int s = rr >> 5, jj = rr & 31;
        float x0 = sb[s][jj][lane * 4 + 0];
        float x1 = sb[s][jj][lane * 4 + 1];
        float x2 = sb[s][jj][lane * 4 + 2];
        float x3 = sb[s][jj][lane * 4 + 3];
        float ss = x0 * x0 + x1 * x1 + x2 * x2 + x3 * x3;
#pragma unroll
        for (int o = 16; o; o >>= 1) ss += __shfl_xor_sync(~0u, ss, o);
        float ri = 1.0f / fmaxf(sqrtf(ss), 1e-12f);
        __nv_bfloat162 p0 = __floats2bfloat162_rn(x0 * ri, x1 * ri);
        __nv_bfloat162 p1 = __floats2bfloat162_rn(x2 * ri, x3 * ri);
        size_t row = (size_t)b * 512 + s * 256 + j0 + jj;
        ((uint2*)g_P)[row * 32 + lane] = make_uint2(*(uint32_t*)&p0, *(uint32_t*)&p1);
    }
}

// ---------------------------------------------------------------------------
// Core: 128-row block x nt col-tiles of 128, K=128, S[row] += sum exp(10d-10).
// 8 warps: warpM = wid>>1 (4 x 32 rows), warpN = wid&1 (2 x 64 cols).
// ---------------------------------------------------------------------------
__device__ __forceinline__ void gemm_ce(const uint4* __restrict__ arows,
                                        const uint4* __restrict__ bbase,
                                        int nt, float* __restrict__ sout, int srow0) {
    extern __shared__ char sm[];
    __nv_bfloat16* As = (__nv_bfloat16*)sm;                  // 128 x STR
    __nv_bfloat16* Bs = (__nv_bfloat16*)(sm + 128 * STR * 2);
    float* red = (float*)(sm + 2 * 128 * STR * 2);           // 256 floats

    int tid = threadIdx.x, lane = tid & 31, wid = tid >> 5;
    int g = lane >> 2, t = lane & 3;
    int warpM = wid >> 1, warpN = wid & 1;
    int woff = warpM * 32, noff = warpN * 64;

    // load A tile (128 rows x 128 bf16)
#pragma unroll
    for (int i = tid; i < 2048; i += 256) {
        int r = i >> 4, cc = i & 15;
        *(uint4*)(As + r * STR + cc * 8) = arows[r * 16 + cc];
    }

    float rs[2][2] = {{0.f, 0.f}, {0.f, 0.f}};

    for (int ct = 0; ct < nt; ct++) {
        __syncthreads();
        const uint4* bsrc = bbase + (size_t)ct * 128 * 16;
#pragma unroll
        for (int i = tid; i < 2048; i += 256) {
            int r = i >> 4, cc = i & 15;
            *(uint4*)(Bs + r * STR + cc * 8) = bsrc[r * 16 + cc];
        }
        __syncthreads();

        float acc[2][8][4];
#pragma unroll
        for (int mi = 0; mi < 2; mi++)
#pragma unroll
            for (int ni = 0; ni < 8; ni++)
#pragma unroll
                for (int q = 0; q < 4; q++) acc[mi][ni][q] = 0.f;

#pragma unroll
        for (int ks = 0; ks < 8; ks++) {
            int k0 = ks * 16;
            uint32_t a[2][4];
#pragma unroll
            for (int mi = 0; mi < 2; mi++) {
                const __nv_bfloat16* ab = As + (woff + mi * 16 + g) * STR + k0 + t * 2;
                a[mi][0] = *(const uint32_t*)(ab);
                a[mi][1] = *(const uint32_t*)(ab + 8 * STR);
                a[mi][2] = *(const uint32_t*)(ab + 8);
                a[mi][3] = *(const uint32_t*)(ab + 8 * STR + 8);
            }
#pragma unroll
            for (int ni = 0; ni < 8; ni++) {
                const __nv_bfloat16* bb = Bs + (noff + ni * 8 + g) * STR + k0 + t * 2;
                uint32_t b[2];
                b[0] = *(const uint32_t*)(bb);
                b[1] = *(const uint32_t*)(bb + 8);
                mma16816(acc[0][ni], a[0], b);
                mma16816(acc[1][ni], a[1], b);
            }
        }

        // epilogue: exp with fixed shift 10
#pragma unroll
        for (int mi = 0; mi < 2; mi++) {
            float s0 = 0.f, s1 = 0.f;
#pragma unroll
            for (int ni = 0; ni < 8; ni++) {
                s0 += ex2f(fmaf(acc[mi][ni][0], L2E10, -L2E10));
                s0 += ex2f(fmaf(acc[mi][ni][1], L2E10, -L2E10));
                s1 += ex2f(fmaf(acc[mi][ni][2], L2E10, -L2E10));
                s1 += ex2f(fmaf(acc[mi][ni][3], L2E10, -L2E10));
            }
            rs[mi][0] += s0;
            rs[mi][1] += s1;
        }
    }

    // reduce over t-lanes (same row)
#pragma unroll
    for (int mi = 0; mi < 2; mi++)
#pragma unroll
        for (int h = 0; h < 2; h++) {
            float v = rs[mi][h];
            v += __shfl_xor_sync(~0u, v, 1);
            v += __shfl_xor_sync(~0u, v, 2);
            rs[mi][h] = v;
        }
    __syncthreads();
    if (t == 0) {
#pragma unroll
        for (int mi = 0; mi < 2; mi++)
#pragma unroll
            for (int h = 0; h < 2; h++)
                red[warpN * 128 + woff + mi * 16 + h * 8 + g] = rs[mi][h];
    }
    __syncthreads();
    if (tid < 128) sout[srow0 + tid] = red[tid] + red[128 + tid];
}

#define SM_DYN (2 * 128 * STR * 2 + 1024)

__global__ void __launch_bounds__(256, 2) k_ins_main() {
    int row0 = blockIdx.x * 128;
    gemm_ce(((const uint4*)g_I) + (size_t)row0 * 16, (const uint4*)g_I,
            128, g_Sins, row0);
}

__global__ void __launch_bounds__(256, 2) k_pat_main() {
    int rb = blockIdx.x;           // 0..3
    int b  = blockIdx.y;           // 0..255
    size_t base = (size_t)b * 512;
    gemm_ce(((const uint4*)g_P) + (base + rb * 128) * 16,
            ((const uint4*)g_P) + base * 16,
            4, g_Spat, (int)base + rb * 128);
}

// ---------------------------------------------------------------------------
// Fixup + row loss: loss_r = 10 + log(S_r - exp(10*diag-10)) - 10*pos
// ---------------------------------------------------------------------------
__device__ __forceinline__ void dots_row(const uint2* a, const uint2* b, int lane,
                                         float& pos, float& dia) {
    uint2 ua = a[lane], ub = b[lane];
    __nv_bfloat162 a0 = *(__nv_bfloat162*)&ua.x, a1 = *(__nv_bfloat162*)&ua.y;
    __nv_bfloat162 b0 = *(__nv_bfloat162*)&ub.x, b1 = *(__nv_bfloat162*)&ub.y;
    float ax0 = __bfloat162float(a0.x), ax1 = __bfloat162float(a0.y);
    float ax2 = __bfloat162float(a1.x), ax3 = __bfloat162float(a1.y);
    float bx0 = __bfloat162float(b0.x), bx1 = __bfloat162float(b0.y);
    float bx2 = __bfloat162float(b1.x), bx3 = __bfloat162float(b1.y);
    pos = ax0 * bx0 + ax1 * bx1 + ax2 * bx2 + ax3 * bx3;
    dia = ax0 * ax0 + ax1 * ax1 + ax2 * ax2 + ax3 * ax3;
#pragma unroll
    for (int o = 16; o; o >>= 1) {
        pos += __shfl_xor_sync(~0u, pos, o);
        dia += __shfl_xor_sync(~0u, dia, o);
    }
}

__global__ void fin_ins() {
    __shared__ float rs[256];
    int tid = threadIdx.x, lane = tid & 31;
    int gw = (blockIdx.x * 256 + tid) >> 5;
    float acc = 0.0f;
    for (int r = gw; r < N_INS; r += 4096) {
        float pos, dia;
        dots_row(((const uint2*)g_I) + (size_t)r * 32,
                 ((const uint2*)g_I) + (size_t)(r ^ B_INS) * 32, lane, pos, dia);
        if (lane == 0) {
            float S = g_Sins[r] - ex2f(fmaf(dia, L2E10, -L2E10));
            acc += 10.0f + logf(S) - 10.0f * pos;
        }
    }
    rs[tid] = acc;
    __syncthreads();
    for (int s = 128; s; s >>= 1) { if (tid < s) rs[tid] += rs[tid + s]; __syncthreads(); }
    if (tid == 0) g_fin1[blockIdx.x] = rs[0];
}

__global__ void fin_patch(const int* __restrict__ c1, const int* __restrict__ c2) {
    __shared__ float rs[256];
    int tid = threadIdx.x, lane = tid & 31;
    int gw = (blockIdx.x * 256 + tid) >> 5;
    float acc = 0.0f;
    for (int r = gw; r < NPROW; r += 8192) {
        int b = r >> 9, rl = r & 511;
        int c = (rl < 256) ? c1[b * 256 + rl] : c2[b * 256 + rl - 256];
        if (c == 0) continue;
        float pos, dia;
        dots_row(((const uint2*)g_P) + (size_t)r * 32,
                 ((const uint2*)g_P) + (size_t)(r ^ 256) * 32, lane, pos, dia);
        if (lane == 0) {
            float S = g_Spat[r] - ex2f(fmaf(dia, L2E10, -L2E10));
            acc += 10.0f + logf(S) - 10.0f * pos;
        }
    }
    rs[tid] = acc;
    __syncthreads();
    for (int s = 128; s; s >>= 1) { if (tid < s) rs[tid] += rs[tid + s]; __syncthreads(); }
    if (tid == 0) g_fin2[blockIdx.x] = rs[0];
}

__global__ void k_combine(const int* __restrict__ c1, const int* __restrict__ c2,
                          float* __restrict__ out) {
    __shared__ float rs[256];
    __shared__ int ri[256];
    int tid = threadIdx.x;
    float a = 0.0f, p = 0.0f;
    int cnt = 0;
    for (int i = tid; i < 512; i += 256) a += g_fin1[i];
    for (int i = tid; i < 1024; i += 256) p += g_fin2[i];
    for (int i = tid; i < 65536; i += 256) cnt += (c1[i] != 0) + (c2[i] != 0);
    rs[tid] = a; ri[tid] = cnt;
    __syncthreads();
    for (int s = 128; s; s >>= 1) {
        if (tid < s) { rs[tid] += rs[tid + s]; ri[tid] += ri[tid + s]; }
        __syncthreads();
    }
    float ins_sum = rs[0];
    int nvalid = ri[0];
    __syncthreads();
    rs[tid] = p;
    __syncthreads();
    for (int s = 128; s; s >>= 1) { if (tid < s) rs[tid] += rs[tid + s]; __syncthreads(); }
    if (tid == 0)
        out[0] = ins_sum / (float)N_INS + rs[0] / (float)nvalid;
}

// ---------------------------------------------------------------------------
extern "C" void kernel_launch(void* const* d_in, const int* in_sizes, int n_in,
                              void* d_out, int out_size) {
    const float* v1  = (const float*)d_in[0];
    const float* v2  = (const float*)d_in[1];
    const float* v1p = (const float*)d_in[2];
    const float* v2p = (const float*)d_in[3];
    const int*   c1  = (const int*)d_in[4];
    const int*   c2  = (const int*)d_in[5];
    float* out = (float*)d_out;

    cudaFuncSetAttribute(k_ins_main, cudaFuncAttributeMaxDynamicSharedMemorySize, SM_DYN);
    cudaFuncSetAttribute(k_pat_main, cudaFuncAttributeMaxDynamicSharedMemorySize, SM_DYN);

    prep_ins<<<512, 256>>>(v1, v2);
    prep_patch<<<dim3(8, 256), 256>>>(v1p, v2p);
    k_ins_main<<<128, 256, SM_DYN>>>();
    k_pat_main<<<dim3(4, 256), 256, SM_DYN>>>();
    fin_ins<<<512, 256>>>();
    fin_patch<<<1024, 256>>>(c1, c2);
    k_combine<<<1, 256>>>(c1, c2, out);
}

// round 4
// speedup vs baseline: 6.4952x; 1.2380x over previous
#include <cuda_runtime.h>
#include <cuda_bf16.h>
#include <cstdint>
#include <math.h>

// ---------------------------------------------------------------------------
// MultiLevelSimCLR via mma.sync.m16n8k16 bf16 + ldmatrix + cp.async pipeline.
// ---------------------------------------------------------------------------

#define B_INS   8192
#define N_INS   16384
#define DDIM    128
#define NPROW   131072
#define L2E10   14.4269504088896340f

// ---- static device scratch ----
__device__ __align__(16) uint32_t g_I[N_INS * 64];   // normalized bf16 instance embs [r][128]
__device__ __align__(16) uint32_t g_P[NPROW * 64];   // normalized bf16 patch embs
__device__ float g_SinsP[2 * N_INS];                 // 2 column-split partials
__device__ float g_Spat[NPROW];
__device__ float g_fin1[512];
__device__ float g_fin2[1024];

__device__ __forceinline__ float ex2f(float x) {
    float y; asm("ex2.approx.f32 %0, %1;" : "=f"(y) : "f"(x)); return y;
}
__device__ __forceinline__ uint32_t smem_u32(const void* p) {
    uint32_t a;
    asm("{ .reg .u64 t; cvta.to.shared.u64 t, %1; cvt.u32.u64 %0, t; }" : "=r"(a) : "l"(p));
    return a;
}
__device__ __forceinline__ void mma16816(float* c, const uint32_t* a, uint32_t b0, uint32_t b1) {
    asm volatile(
        "mma.sync.aligned.m16n8k16.row.col.f32.bf16.bf16.f32 "
        "{%0,%1,%2,%3}, {%4,%5,%6,%7}, {%8,%9}, {%0,%1,%2,%3};"
        : "+f"(c[0]), "+f"(c[1]), "+f"(c[2]), "+f"(c[3])
        : "r"(a[0]), "r"(a[1]), "r"(a[2]), "r"(a[3]), "r"(b0), "r"(b1));
}
__device__ __forceinline__ void ldsm_x4(uint32_t* r, uint32_t addr) {
    asm volatile("ldmatrix.sync.aligned.m8n8.x4.shared.b16 {%0,%1,%2,%3}, [%4];"
        : "=r"(r[0]), "=r"(r[1]), "=r"(r[2]), "=r"(r[3]) : "r"(addr));
}
#define CP_ASYNC16(dst, src) asm volatile("cp.async.cg.shared.global [%0], [%1], 16;" :: "r"(dst), "l"(src))
#define CP_COMMIT()  asm volatile("cp.async.commit_group;" ::: "memory")
#define CP_WAIT0()   asm volatile("cp.async.wait_group 0;" ::: "memory")
#define CP_WAIT1()   asm volatile("cp.async.wait_group 1;" ::: "memory")

// SMEM map: A tile 32KB @0, B0 @32768, B1 @65536, red @98304
#define SM_A    0
#define SM_B0   32768u
#define SM_RED  98304
#define SM_DYN  (98304 + 1024)

// Copy one 128x128 bf16 tile (128 rows x 256B) global->smem, chunk-swizzled.
__device__ __forceinline__ void cpa_tile(uint32_t dst, const char* __restrict__ src) {
    int tid = threadIdx.x;
#pragma unroll
    for (int i = 0; i < 8; i++) {
        int c = tid + i * 256;
        int r = c >> 4, cc = c & 15;
        uint32_t d = dst + r * 256 + (((uint32_t)(cc ^ (r & 7))) << 4);
        CP_ASYNC16(d, src + r * 256 + cc * 16);
    }
}

// ---------------------------------------------------------------------------
// Prep: normalize + bf16-convert instance embeddings
// ---------------------------------------------------------------------------
__global__ void prep_ins(const float* __restrict__ v1, const float* __restrict__ v2) {
    int lane = threadIdx.x & 31;
    int gw = (blockIdx.x * blockDim.x + threadIdx.x) >> 5;
    for (int r = gw; r < N_INS; r += 4096) {
        const float* src = (r < B_INS) ? v1 + (size_t)r * DDIM : v2 + (size_t)(r - B_INS) * DDIM;
        float4 x = ((const float4*)src)[lane];
        float ss = x.x * x.x + x.y * x.y + x.z * x.z + x.w * x.w;
#pragma unroll
        for (int o = 16; o; o >>= 1) ss += __shfl_xor_sync(~0u, ss, o);
        float ri = 1.0f / fmaxf(sqrtf(ss), 1e-12f);
        __nv_bfloat162 p0 = __floats2bfloat162_rn(x.x * ri, x.y * ri);
        __nv_bfloat162 p1 = __floats2bfloat162_rn(x.z * ri, x.w * ri);
        ((uint2*)g_I)[(size_t)r * 32 + lane] = make_uint2(*(uint32_t*)&p0, *(uint32_t*)&p1);
    }
}

// ---------------------------------------------------------------------------
// Prep: patch embeddings ([b][k][j] -> normalized bf16 [b*512+j][k])
// ---------------------------------------------------------------------------
__global__ void prep_patch(const float* __restrict__ v1p, const float* __restrict__ v2p) {
    __shared__ float sb[2][32][129];
    int tid = threadIdx.x, lane = tid & 31, wid = tid >> 5;
    int j0 = blockIdx.x * 32;
    int b = blockIdx.y;
    const float* srcs[2] = { v1p + (size_t)b * DDIM * 256, v2p + (size_t)b * DDIM * 256 };
#pragma unroll
    for (int s = 0; s < 2; s++) {
        const float* src = srcs[s];
        for (int i = 0; i < 16; i++) {
            int idx = tid + i * 256;
            int k = idx >> 5, jj = idx & 31;
            sb[s][jj][k] = src[(size_t)k * 256 + j0 + jj];
        }
    }
    __syncthreads();
    for (int t = 0; t < 8; t++) {
        int rr = wid * 8 + t;
        int s = rr >> 5, jj = rr & 31;
        float x0 = sb[s][jj][lane * 4 + 0];
        float x1 = sb[s][jj][lane * 4 + 1];
        float x2 = sb[s][jj][lane * 4 + 2];
        float x3 = sb[s][jj][lane * 4 + 3];
        float ss = x0 * x0 + x1 * x1 + x2 * x2 + x3 * x3;
#pragma unroll
        for (int o = 16; o; o >>= 1) ss += __shfl_xor_sync(~0u, ss, o);
        float ri = 1.0f / fmaxf(sqrtf(ss), 1e-12f);
        __nv_bfloat162 p0 = __floats2bfloat162_rn(x0 * ri, x1 * ri);
        __nv_bfloat162 p1 = __floats2bfloat162_rn(x2 * ri, x3 * ri);
        size_t row = (size_t)b * 512 + s * 256 + j0 + jj;
        ((uint2*)g_P)[row * 32 + lane] = make_uint2(*(uint32_t*)&p0, *(uint32_t*)&p1);
    }
}

// ---------------------------------------------------------------------------
// Core: 128-row block x nt 128-col tiles, K=128; S[row] += sum exp(10d - 10).
// 8 warps as 4(M) x 2(N). ldmatrix fragments, cp.async double-buffered B.
// ---------------------------------------------------------------------------
__device__ __forceinline__ void gemm_ce(const char* __restrict__ arows,
                                        const char* __restrict__ bbase,
                                        int nt, float* __restrict__ sout, int srow0) {
    extern __shared__ char sm[];
    uint32_t sbu = smem_u32(sm);
    float* red = (float*)(sm + SM_RED);

    int tid = threadIdx.x, lane = tid & 31, wid = tid >> 5;
    int g = lane >> 2, t = lane & 3;
    int l7 = lane & 7, l15 = lane & 15, hi = lane >> 4;
    int warpM = wid >> 1, warpN = wid & 1;
    int woff = warpM * 32, noff = warpN * 64;

    // ldmatrix row-base addresses (chunk offset added per ks)
    uint32_t aAddr0 = sbu + SM_A + (uint32_t)(woff + l15) * 256;
    uint32_t aAddr1 = aAddr0 + 16 * 256;
    uint32_t bRow = (uint32_t)(noff + l15) * 256;   // add buffer base later

    // prologue: A + B0 (group), B1 (group)
    cpa_tile(sbu + SM_A, arows);
    cpa_tile(sbu + SM_B0, bbase);
    CP_COMMIT();
    if (nt > 1) { cpa_tile(sbu + SM_B0 + 32768u, bbase + 32768); CP_COMMIT(); }

    float rs[2][2] = {{0.f, 0.f}, {0.f, 0.f}};

    for (int ct = 0; ct < nt; ct++) {
        if (ct + 1 < nt) CP_WAIT1(); else CP_WAIT0();
        __syncthreads();

        uint32_t bbuf = sbu + SM_B0 + ((uint32_t)(ct & 1) << 15);

        float acc[2][8][4];
#pragma unroll
        for (int mi = 0; mi < 2; mi++)
#pragma unroll
            for (int ni = 0; ni < 8; ni++)
#pragma unroll
                for (int q = 0; q < 4; q++) acc[mi][ni][q] = 0.f;

#pragma unroll
        for (int ks = 0; ks < 8; ks++) {
            uint32_t coff = (uint32_t)((((ks << 1) | hi) ^ l7) << 4);
            uint32_t a[2][4];
            ldsm_x4(a[0], aAddr0 + coff);
            ldsm_x4(a[1], aAddr1 + coff);
            uint32_t b[4][4];
#pragma unroll
            for (int nj = 0; nj < 4; nj++)
                ldsm_x4(b[nj], bbuf + bRow + nj * 16 * 256 + coff);
#pragma unroll
            for (int nj = 0; nj < 4; nj++) {
                mma16816(acc[0][nj * 2 + 0], a[0], b[nj][0], b[nj][2]);
                mma16816(acc[0][nj * 2 + 1], a[0], b[nj][1], b[nj][3]);
                mma16816(acc[1][nj * 2 + 0], a[1], b[nj][0], b[nj][2]);
                mma16816(acc[1][nj * 2 + 1], a[1], b[nj][1], b[nj][3]);
            }
        }

        // epilogue: fixed-shift exp, accumulate row sums
#pragma unroll
        for (int mi = 0; mi < 2; mi++) {
            float s0 = 0.f, s1 = 0.f;
#pragma unroll
            for (int ni = 0; ni < 8; ni++) {
                s0 += ex2f(fmaf(acc[mi][ni][0], L2E10, -L2E10));
                s0 += ex2f(fmaf(acc[mi][ni][1], L2E10, -L2E10));
                s1 += ex2f(fmaf(acc[mi][ni][2], L2E10, -L2E10));
                s1 += ex2f(fmaf(acc[mi][ni][3], L2E10, -L2E10));
            }
            rs[mi][0] += s0;
            rs[mi][1] += s1;
        }

        __syncthreads();
        if (ct + 2 < nt) {
            cpa_tile(bbuf, bbase + (size_t)(ct + 2) * 32768);
            CP_COMMIT();
        }
    }

    // reduce over t-lanes (4 lanes share a row)
#pragma unroll
    for (int mi = 0; mi < 2; mi++)
#pragma unroll
        for (int h = 0; h < 2; h++) {
            float v = rs[mi][h];
            v += __shfl_xor_sync(~0u, v, 1);
            v += __shfl_xor_sync(~0u, v, 2);
            rs[mi][h] = v;
        }
    if (t == 0) {
#pragma unroll
        for (int mi = 0; mi < 2; mi++)
#pragma unroll
            for (int h = 0; h < 2; h++)
                red[warpN * 128 + woff + mi * 16 + h * 8 + g] = rs[mi][h];
    }
    __syncthreads();
    if (tid < 128) sout[srow0 + tid] = red[tid] + red[128 + tid];
}

__global__ void __launch_bounds__(256, 2) k_ins_main() {
    int row0 = blockIdx.x * 128;
    int split = blockIdx.y;                       // 0,1 -> column halves
    gemm_ce((const char*)g_I + (size_t)row0 * 256,
            (const char*)g_I + (size_t)split * 64 * 32768,
            64, g_SinsP + split * N_INS, row0);
}

__global__ void __launch_bounds__(256, 2) k_pat_main() {
    int rb = blockIdx.x;
    int b  = blockIdx.y;
    size_t base = (size_t)b * 512;
    gemm_ce((const char*)g_P + (base + rb * 128) * 256,
            (const char*)g_P + base * 256,
            4, g_Spat, (int)base + rb * 128);
}

// ---------------------------------------------------------------------------
// Fixup + row loss: loss_r = 10 + log(S_r - exp(10*diag-10)) - 10*pos
// ---------------------------------------------------------------------------
__device__ __forceinline__ void dots_row(const uint2* a, const uint2* b, int lane,
                                         float& pos, float& dia) {
    uint2 ua = a[lane], ub = b[lane];
    __nv_bfloat162 a0 = *(__nv_bfloat162*)&ua.x, a1 = *(__nv_bfloat162*)&ua.y;
    __nv_bfloat162 b0 = *(__nv_bfloat162*)&ub.x, b1 = *(__nv_bfloat162*)&ub.y;
    float ax0 = __bfloat162float(a0.x), ax1 = __bfloat162float(a0.y);
    float ax2 = __bfloat162float(a1.x), ax3 = __bfloat162float(a1.y);
    float bx0 = __bfloat162float(b0.x), bx1 = __bfloat162float(b0.y);
    float bx2 = __bfloat162float(b1.x), bx3 = __bfloat162float(b1.y);
    pos = ax0 * bx0 + ax1 * bx1 + ax2 * bx2 + ax3 * bx3;
    dia = ax0 * ax0 + ax1 * ax1 + ax2 * ax2 + ax3 * ax3;
#pragma unroll
    for (int o = 16; o; o >>= 1) {
        pos += __shfl_xor_sync(~0u, pos, o);
        dia += __shfl_xor_sync(~0u, dia, o);
    }
}

__global__ void fin_ins() {
    __shared__ float rs[256];
    int tid = threadIdx.x, lane = tid & 31;
    int gw = (blockIdx.x * 256 + tid) >> 5;
    float acc = 0.0f;
    for (int r = gw; r < N_INS; r += 4096) {
        float pos, dia;
        dots_row(((const uint2*)g_I) + (size_t)r * 32,
                 ((const uint2*)g_I) + (size_t)(r ^ B_INS) * 32, lane, pos, dia);
        if (lane == 0) {
            float S = g_SinsP[r] + g_SinsP[N_INS + r] - ex2f(fmaf(dia, L2E10, -L2E10));
            acc += 10.0f + logf(S) - 10.0f * pos;
        }
    }
    rs[tid] = acc;
    __syncthreads();
    for (int s = 128; s; s >>= 1) { if (tid < s) rs[tid] += rs[tid + s]; __syncthreads(); }
    if (tid == 0) g_fin1[blockIdx.x] = rs[0];
}

__global__ void fin_patch(const int* __restrict__ c1, const int* __restrict__ c2) {
    __shared__ float rs[256];
    int tid = threadIdx.x, lane = tid & 31;
    int gw = (blockIdx.x * 256 + tid) >> 5;
    float acc = 0.0f;
    for (int r = gw; r < NPROW; r += 8192) {
        int b = r >> 9, rl = r & 511;
        int c = (rl < 256) ? c1[b * 256 + rl] : c2[b * 256 + rl - 256];
        if (c == 0) continue;
        float pos, dia;
        dots_row(((const uint2*)g_P) + (size_t)r * 32,
                 ((const uint2*)g_P) + (size_t)(r ^ 256) * 32, lane, pos, dia);
        if (lane == 0) {
            float S = g_Spat[r] - ex2f(fmaf(dia, L2E10, -L2E10));
            acc += 10.0f + logf(S) - 10.0f * pos;
        }
    }
    rs[tid] = acc;
    __syncthreads();
    for (int s = 128; s; s >>= 1) { if (tid < s) rs[tid] += rs[tid + s]; __syncthreads(); }
    if (tid == 0) g_fin2[blockIdx.x] = rs[0];
}

__global__ void k_combine(const int* __restrict__ c1, const int* __restrict__ c2,
                          float* __restrict__ out) {
    __shared__ float rs[256];
    __shared__ int ri[256];
    int tid = threadIdx.x;
    float a = 0.0f, p = 0.0f;
    int cnt = 0;
    for (int i = tid; i < 512; i += 256) a += g_fin1[i];
    for (int i = tid; i < 1024; i += 256) p += g_fin2[i];
    for (int i = tid; i < 65536; i += 256) cnt += (c1[i] != 0) + (c2[i] != 0);
    rs[tid] = a; ri[tid] = cnt;
    __syncthreads();
    for (int s = 128; s; s >>= 1) {
        if (tid < s) { rs[tid] += rs[tid + s]; ri[tid] += ri[tid + s]; }
        __syncthreads();
    }
    float ins_sum = rs[0];
    int nvalid = ri[0];
    __syncthreads();
    rs[tid] = p;
    __syncthreads();
    for (int s = 128; s; s >>= 1) { if (tid < s) rs[tid] += rs[tid + s]; __syncthreads(); }
    if (tid == 0)
        out[0] = ins_sum / (float)N_INS + rs[0] / (float)nvalid;
}

// ---------------------------------------------------------------------------
extern "C" void kernel_launch(void* const* d_in, const int* in_sizes, int n_in,
                              void* d_out, int out_size) {
    const float* v1  = (const float*)d_in[0];
    const float* v2  = (const float*)d_in[1];
    const float* v1p = (const float*)d_in[2];
    const float* v2p = (const float*)d_in[3];
    const int*   c1  = (const int*)d_in[4];
    const int*   c2  = (const int*)d_in[5];
    float* out = (float*)d_out;

    cudaFuncSetAttribute(k_ins_main, cudaFuncAttributeMaxDynamicSharedMemorySize, SM_DYN);
    cudaFuncSetAttribute(k_pat_main, cudaFuncAttributeMaxDynamicSharedMemorySize, SM_DYN);

    prep_ins<<<512, 256>>>(v1, v2);
    prep_patch<<<dim3(8, 256), 256>>>(v1p, v2p);
    k_ins_main<<<dim3(128, 2), 256, SM_DYN>>>();
    k_pat_main<<<dim3(4, 256), 256, SM_DYN>>>();
    fin_ins<<<512, 256>>>();
    fin_patch<<<1024, 256>>>(c1, c2);
    k_combine<<<1, 256>>>(c1, c2, out);
}

// round 5
// speedup vs baseline: 6.9192x; 1.0653x over previous
#include <cuda_runtime.h>
#include <cuda_bf16.h>
#include <cuda_fp16.h>
#include <cstdint>
#include <math.h>

// ---------------------------------------------------------------------------
// MultiLevelSimCLR via mma.sync.m16n8k16 bf16 + ldmatrix + cp.async pipeline.
// Epilogue in packed f16x2 (ex2.approx.f16x2) to halve MUFU pressure.
// ---------------------------------------------------------------------------

#define B_INS   8192
#define N_INS   16384
#define DDIM    128
#define NPROW   131072
#define L2E10   14.4269504088896340f

// ---- static device scratch ----
__device__ __align__(16) uint32_t g_I[N_INS * 64];   // normalized bf16 instance embs [r][128]
__device__ __align__(16) uint32_t g_P[NPROW * 64];   // normalized bf16 patch embs
__device__ float g_SinsP[2 * N_INS];                 // 2 column-split partials
__device__ float g_Spat[NPROW];
__device__ float g_fin1[512];
__device__ float g_fin2[1024];

__device__ __forceinline__ float ex2f(float x) {
    float y; asm("ex2.approx.f32 %0, %1;" : "=f"(y) : "f"(x)); return y;
}
__device__ __forceinline__ __half2 h2ex2(__half2 x) {
    uint32_t xi = *(uint32_t*)&x, yi;
    asm("ex2.approx.f16x2 %0, %1;" : "=r"(yi) : "r"(xi));
    return *(__half2*)&yi;
}
__device__ __forceinline__ uint32_t smem_u32(const void* p) {
    uint32_t a;
    asm("{ .reg .u64 t; cvta.to.shared.u64 t, %1; cvt.u32.u64 %0, t; }" : "=r"(a) : "l"(p));
    return a;
}
__device__ __forceinline__ void mma16816(float* c, const uint32_t* a, uint32_t b0, uint32_t b1) {
    asm volatile(
        "mma.sync.aligned.m16n8k16.row.col.f32.bf16.bf16.f32 "
        "{%0,%1,%2,%3}, {%4,%5,%6,%7}, {%8,%9}, {%0,%1,%2,%3};"
        : "+f"(c[0]), "+f"(c[1]), "+f"(c[2]), "+f"(c[3])
        : "r"(a[0]), "r"(a[1]), "r"(a[2]), "r"(a[3]), "r"(b0), "r"(b1));
}
__device__ __forceinline__ void ldsm_x4(uint32_t* r, uint32_t addr) {
    asm volatile("ldmatrix.sync.aligned.m8n8.x4.shared.b16 {%0,%1,%2,%3}, [%4];"
        : "=r"(r[0]), "=r"(r[1]), "=r"(r[2]), "=r"(r[3]) : "r"(addr));
}
#define CP_ASYNC16(dst, src) asm volatile("cp.async.cg.shared.global [%0], [%1], 16;" :: "r"(dst), "l"(src))
#define CP_COMMIT()  asm volatile("cp.async.commit_group;" ::: "memory")
#define CP_WAIT0()   asm volatile("cp.async.wait_group 0;" ::: "memory")
#define CP_WAIT1()   asm volatile("cp.async.wait_group 1;" ::: "memory")

// SMEM map: A tile 32KB @0, B0 @32768, B1 @65536, red @98304
#define SM_A    0
#define SM_B0   32768u
#define SM_RED  98304
#define SM_DYN  (98304 + 1024)

// Copy one 128x128 bf16 tile (128 rows x 256B) global->smem, chunk-swizzled.
__device__ __forceinline__ void cpa_tile(uint32_t dst, const char* __restrict__ src) {
    int tid = threadIdx.x;
#pragma unroll
    for (int i = 0; i < 8; i++) {
        int c = tid + i * 256;
        int r = c >> 4, cc = c & 15;
        uint32_t d = dst + r * 256 + (((uint32_t)(cc ^ (r & 7))) << 4);
        CP_ASYNC16(d, src + r * 256 + cc * 16);
    }
}

// ---------------------------------------------------------------------------
// Prep: normalize + bf16-convert instance embeddings
// ---------------------------------------------------------------------------
__global__ void prep_ins(const float* __restrict__ v1, const float* __restrict__ v2) {
    int lane = threadIdx.x & 31;
    int gw = (blockIdx.x * blockDim.x + threadIdx.x) >> 5;
    for (int r = gw; r < N_INS; r += 4096) {
        const float* src = (r < B_INS) ? v1 + (size_t)r * DDIM : v2 + (size_t)(r - B_INS) * DDIM;
        float4 x = ((const float4*)src)[lane];
        float ss = x.x * x.x + x.y * x.y + x.z * x.z + x.w * x.w;
#pragma unroll
        for (int o = 16; o; o >>= 1) ss += __shfl_xor_sync(~0u, ss, o);
        float ri = 1.0f / fmaxf(sqrtf(ss), 1e-12f);
        __nv_bfloat162 p0 = __floats2bfloat162_rn(x.x * ri, x.y * ri);
        __nv_bfloat162 p1 = __floats2bfloat162_rn(x.z * ri, x.w * ri);
        ((uint2*)g_I)[(size_t)r * 32 + lane] = make_uint2(*(uint32_t*)&p0, *(uint32_t*)&p1);
    }
}

// ---------------------------------------------------------------------------
// Prep: patch embeddings ([b][k][j] -> normalized bf16 [b*512+j][k])
// ---------------------------------------------------------------------------
__global__ void prep_patch(const float* __restrict__ v1p, const float* __restrict__ v2p) {
    __shared__ float sb[2][32][129];
    int tid = threadIdx.x, lane = tid & 31, wid = tid >> 5;
    int j0 = blockIdx.x * 32;
    int b = blockIdx.y;
    const float* srcs[2] = { v1p + (size_t)b * DDIM * 256, v2p + (size_t)b * DDIM * 256 };
#pragma unroll
    for (int s = 0; s < 2; s++) {
        const float* src = srcs[s];
        for (int i = 0; i < 16; i++) {
            int idx = tid + i * 256;
            int k = idx >> 5, jj = idx & 31;
            sb[s][jj][k] = src[(size_t)k * 256 + j0 + jj];
        }
    }
    __syncthreads();
    for (int t = 0; t < 8; t++) {
        int rr = wid * 8 + t;
        int s = rr >> 5, jj = rr & 31;
        float x0 = sb[s][jj][lane * 4 + 0];
        float x1 = sb[s][jj][lane * 4 + 1];
        float x2 = sb[s][jj][lane * 4 + 2];
        float x3 = sb[s][jj][lane * 4 + 3];
        float ss = x0 * x0 + x1 * x1 + x2 * x2 + x3 * x3;
#pragma unroll
        for (int o = 16; o; o >>= 1) ss += __shfl_xor_sync(~0u, ss, o);
        float ri = 1.0f / fmaxf(sqrtf(ss), 1e-12f);
        __nv_bfloat162 p0 = __floats2bfloat162_rn(x0 * ri, x1 * ri);
        __nv_bfloat162 p1 = __floats2bfloat162_rn(x2 * ri, x3 * ri);
        size_t row = (size_t)b * 512 + s * 256 + j0 + jj;
        ((uint2*)g_P)[row * 32 + lane] = make_uint2(*(uint32_t*)&p0, *(uint32_t*)&p1);
    }
}

// ---------------------------------------------------------------------------
// Core: 128-row block x nt 128-col tiles, K=128; S[row] += sum exp(10d - 10).
// 8 warps as 4(M) x 2(N). ldmatrix fragments, cp.async double-buffered B,
// packed f16x2 epilogue.
// ---------------------------------------------------------------------------
__device__ __forceinline__ void gemm_ce(const char* __restrict__ arows,
                                        const char* __restrict__ bbase,
                                        int nt, float* __restrict__ sout, int srow0) {
    extern __shared__ char sm[];
    uint32_t sbu = smem_u32(sm);
    float* red = (float*)(sm + SM_RED);

    int tid = threadIdx.x, lane = tid & 31, wid = tid >> 5;
    int g = lane >> 2, t = lane & 3;
    int l7 = lane & 7, l15 = lane & 15, hi = lane >> 4;
    int warpM = wid >> 1, warpN = wid & 1;
    int woff = warpM * 32, noff = warpN * 64;

    const __half2 hscale = __floats2half2_rn(L2E10, L2E10);
    const __half2 hbias  = __floats2half2_rn(-L2E10, -L2E10);

    uint32_t aAddr0 = sbu + SM_A + (uint32_t)(woff + l15) * 256;
    uint32_t aAddr1 = aAddr0 + 16 * 256;
    uint32_t bRow = (uint32_t)(noff + l15) * 256;

    cpa_tile(sbu + SM_A, arows);
    cpa_tile(sbu + SM_B0, bbase);
    CP_COMMIT();
    if (nt > 1) { cpa_tile(sbu + SM_B0 + 32768u, bbase + 32768); CP_COMMIT(); }

    float rs[2][2] = {{0.f, 0.f}, {0.f, 0.f}};

    for (int ct = 0; ct < nt; ct++) {
        if (ct + 1 < nt) CP_WAIT1(); else CP_WAIT0();
        __syncthreads();

        uint32_t bbuf = sbu + SM_B0 + ((uint32_t)(ct & 1) << 15);

        float acc[2][8][4];
#pragma unroll
        for (int mi = 0; mi < 2; mi++)
#pragma unroll
            for (int ni = 0; ni < 8; ni++)
#pragma unroll
                for (int q = 0; q < 4; q++) acc[mi][ni][q] = 0.f;

#pragma unroll
        for (int ks = 0; ks < 8; ks++) {
            uint32_t coff = (uint32_t)((((ks << 1) | hi) ^ l7) << 4);
            uint32_t a[2][4];
            ldsm_x4(a[0], aAddr0 + coff);
            ldsm_x4(a[1], aAddr1 + coff);
            uint32_t b[4][4];
#pragma unroll
            for (int nj = 0; nj < 4; nj++)
                ldsm_x4(b[nj], bbuf + bRow + nj * 16 * 256 + coff);
#pragma unroll
            for (int nj = 0; nj < 4; nj++) {
                mma16816(acc[0][nj * 2 + 0], a[0], b[nj][0], b[nj][2]);
                mma16816(acc[0][nj * 2 + 1], a[0], b[nj][1], b[nj][3]);
                mma16816(acc[1][nj * 2 + 0], a[1], b[nj][0], b[nj][2]);
                mma16816(acc[1][nj * 2 + 1], a[1], b[nj][1], b[nj][3]);
            }
        }

        // free this B buffer for the prefetch, then overlap copy with epilogue
        __syncthreads();
        if (ct + 2 < nt) {
            cpa_tile(bbuf, bbase + (size_t)(ct + 2) * 32768);
            CP_COMMIT();
        }

        // epilogue: packed f16x2 exp with fixed shift 10
#pragma unroll
        for (int mi = 0; mi < 2; mi++) {
#pragma unroll
            for (int h = 0; h < 2; h++) {
                __half2 e[8];
#pragma unroll
                for (int ni = 0; ni < 8; ni++) {
                    __half2 v = __floats2half2_rn(acc[mi][ni][h * 2], acc[mi][ni][h * 2 + 1]);
                    e[ni] = h2ex2(__hfma2(v, hscale, hbias));
                }
                e[0] = __hadd2(e[0], e[1]); e[2] = __hadd2(e[2], e[3]);
                e[4] = __hadd2(e[4], e[5]); e[6] = __hadd2(e[6], e[7]);
                e[0] = __hadd2(e[0], e[2]); e[4] = __hadd2(e[4], e[6]);
                e[0] = __hadd2(e[0], e[4]);
                rs[mi][h] += __low2float(e[0]) + __high2float(e[0]);
            }
        }
    }

    // reduce over t-lanes (4 lanes share a row)
#pragma unroll
    for (int mi = 0; mi < 2; mi++)
#pragma unroll
        for (int h = 0; h < 2; h++) {
            float v = rs[mi][h];
            v += __shfl_xor_sync(~0u, v, 1);
            v += __shfl_xor_sync(~0u, v, 2);
            rs[mi][h] = v;
        }
    __syncthreads();
    if (t == 0) {
#pragma unroll
        for (int mi = 0; mi < 2; mi++)
#pragma unroll
            for (int h = 0; h < 2; h++)
                red[warpN * 128 + woff + mi * 16 + h * 8 + g] = rs[mi][h];
    }
    __syncthreads();
    if (tid < 128) sout[srow0 + tid] = red[tid] + red[128 + tid];
}

__global__ void __launch_bounds__(256, 2) k_ins_main() {
    int row0 = blockIdx.x * 128;
    int split = blockIdx.y;
    gemm_ce((const char*)g_I + (size_t)row0 * 256,
            (const char*)g_I + (size_t)split * 64 * 32768,
            64, g_SinsP + split * N_INS, row0);
}

__global__ void __launch_bounds__(256, 2) k_pat_main() {
    int rb = blockIdx.x;
    int b  = blockIdx.y;
    size_t base = (size_t)b * 512;
    gemm_ce((const char*)g_P + (base + rb * 128) * 256,
            (const char*)g_P + base * 256,
            4, g_Spat, (int)base + rb * 128);
}

// ---------------------------------------------------------------------------
// Fixup + row loss: loss_r = 10 + log(S_r - exp(10*diag-10)) - 10*pos
// ---------------------------------------------------------------------------
__device__ __forceinline__ void dots_row(const uint2* a, const uint2* b, int lane,
                                         float& pos, float& dia) {
    uint2 ua = a[lane], ub = b[lane];
    __nv_bfloat162 a0 = *(__nv_bfloat162*)&ua.x, a1 = *(__nv_bfloat162*)&ua.y;
    __nv_bfloat162 b0 = *(__nv_bfloat162*)&ub.x, b1 = *(__nv_bfloat162*)&ub.y;
    float ax0 = __bfloat162float(a0.x), ax1 = __bfloat162float(a0.y);
    float ax2 = __bfloat162float(a1.x), ax3 = __bfloat162float(a1.y);
    float bx0 = __bfloat162float(b0.x), bx1 = __bfloat162float(b0.y);
    float bx2 = __bfloat162float(b1.x), bx3 = __bfloat162float(b1.y);
    pos = ax0 * bx0 + ax1 * bx1 + ax2 * bx2 + ax3 * bx3;
    dia = ax0 * ax0 + ax1 * ax1 + ax2 * ax2 + ax3 * ax3;
#pragma unroll
    for (int o = 16; o; o >>= 1) {
        pos += __shfl_xor_sync(~0u, pos, o);
        dia += __shfl_xor_sync(~0u, dia, o);
    }
}

__global__ void fin_ins() {
    __shared__ float rs[256];
    int tid = threadIdx.x, lane = tid & 31;
    int gw = (blockIdx.x * 256 + tid) >> 5;
    float acc = 0.0f;
    for (int r = gw; r < N_INS; r += 4096) {
        float pos, dia;
        dots_row(((const uint2*)g_I) + (size_t)r * 32,
                 ((const uint2*)g_I) + (size_t)(r ^ B_INS) * 32, lane, pos, dia);
        if (lane == 0) {
            // subtract f16-rounded diag term (matches what the main kernel summed)
            float darg = fmaf(dia, L2E10, -L2E10);
            float dterm = __half2float(h2ex2(__floats2half2_rn(darg, darg)).x);
            float S = g_SinsP[r] + g_SinsP[N_INS + r] - dterm;
            acc += 10.0f + logf(S) - 10.0f * pos;
        }
    }
    rs[tid] = acc;
    __syncthreads();
    for (int s = 128; s; s >>= 1) { if (tid < s) rs[tid] += rs[tid + s]; __syncthreads(); }
    if (tid == 0) g_fin1[blockIdx.x] = rs[0];
}

__global__ void fin_patch(const int* __restrict__ c1, const int* __restrict__ c2) {
    __shared__ float rs[256];
    int tid = threadIdx.x, lane = tid & 31;
    int gw = (blockIdx.x * 256 + tid) >> 5;
    float acc = 0.0f;
    for (int r = gw; r < NPROW; r += 8192) {
        int b = r >> 9, rl = r & 511;
        int c = (rl < 256) ? c1[b * 256 + rl] : c2[b * 256 + rl - 256];
        if (c == 0) continue;
        float pos, dia;
        dots_row(((const uint2*)g_P) + (size_t)r * 32,
                 ((const uint2*)g_P) + (size_t)(r ^ 256) * 32, lane, pos, dia);
        if (lane == 0) {
            float darg = fmaf(dia, L2E10, -L2E10);
            float dterm = __half2float(h2ex2(__floats2half2_rn(darg, darg)).x);
            float S = g_Spat[r] - dterm;
            acc += 10.0f + logf(S) - 10.0f * pos;
        }
    }
    rs[tid] = acc;
    __syncthreads();
    for (int s = 128; s; s >>= 1) { if (tid < s) rs[tid] += rs[tid + s]; __syncthreads(); }
    if (tid == 0) g_fin2[blockIdx.x] = rs[0];
}

__global__ void k_combine(const int* __restrict__ c1, const int* __restrict__ c2,
                          float* __restrict__ out) {
    __shared__ float rs[256];
    __shared__ int ri[256];
    int tid = threadIdx.x;
    float a = 0.0f, p = 0.0f;
    int cnt = 0;
    for (int i = tid; i < 512; i += 256) a += g_fin1[i];
    for (int i = tid; i < 1024; i += 256) p += g_fin2[i];
    for (int i = tid; i < 65536; i += 256) cnt += (c1[i] != 0) + (c2[i] != 0);
    rs[tid] = a; ri[tid] = cnt;
    __syncthreads();
    for (int s = 128; s; s >>= 1) {
        if (tid < s) { rs[tid] += rs[tid + s]; ri[tid] += ri[tid + s]; }
        __syncthreads();
    }
    float ins_sum = rs[0];
    int nvalid = ri[0];
    __syncthreads();
    rs[tid] = p;
    __syncthreads();
    for (int s = 128; s; s >>= 1) { if (tid < s) rs[tid] += rs[tid + s]; __syncthreads(); }
    if (tid == 0)
        out[0] = ins_sum / (float)N_INS + rs[0] / (float)nvalid;
}

// ---------------------------------------------------------------------------
extern "C" void kernel_launch(void* const* d_in, const int* in_sizes, int n_in,
                              void* d_out, int out_size) {
    const float* v1  = (const float*)d_in[0];
    const float* v2  = (const float*)d_in[1];
    const float* v1p = (const float*)d_in[2];
    const float* v2p = (const float*)d_in[3];
    const int*   c1  = (const int*)d_in[4];
    const int*   c2  = (const int*)d_in[5];
    float* out = (float*)d_out;

    cudaFuncSetAttribute(k_ins_main, cudaFuncAttributeMaxDynamicSharedMemorySize, SM_DYN);
    cudaFuncSetAttribute(k_pat_main, cudaFuncAttributeMaxDynamicSharedMemorySize, SM_DYN);

    prep_ins<<<512, 256>>>(v1, v2);
    prep_patch<<<dim3(8, 256), 256>>>(v1p, v2p);
    k_ins_main<<<dim3(128, 2), 256, SM_DYN>>>();
    k_pat_main<<<dim3(4, 256), 256, SM_DYN>>>();
    fin_ins<<<512, 256>>>();
    fin_patch<<<1024, 256>>>(c1, c2);
    k_combine<<<1, 256>>>(c1, c2, out);
}

// round 6
// speedup vs baseline: 9.2815x; 1.3414x over previous
#include <cuda_runtime.h>
#include <cuda_bf16.h>
#include <cstdint>
#include <math.h>

// ---------------------------------------------------------------------------
// MultiLevelSimCLR, symmetric-tile HMMA version.
// Gram matrices are symmetric: compute only upper-triangular 128x128 tiles;
// each tile emits row partials (block bi) AND column partials (block bj).
// ---------------------------------------------------------------------------

#define B_INS   8192
#define N_INS   16384
#define DDIM    128
#define NPROW   131072
#define L2E10   14.4269504088896340f

// ---- static device scratch ----
__device__ __align__(16) uint32_t g_I[N_INS * 64];     // bf16 instance embs [r][128]
__device__ __align__(16) uint32_t g_P[NPROW * 64];     // bf16 patch embs
__device__ float g_part[128 * 128 * 128];              // instance block partials [bi][bj][m]
__device__ float g_ppart[256 * 16 * 128];              // patch block partials [b][bi*4+bj][m]
__device__ float g_fin1[512];
__device__ float g_fin2[1024];

__device__ __forceinline__ float ex2f(float x) {
    float y; asm("ex2.approx.f32 %0, %1;" : "=f"(y) : "f"(x)); return y;
}
__device__ __forceinline__ uint32_t smem_u32(const void* p) {
    uint32_t a;
    asm("{ .reg .u64 t; cvta.to.shared.u64 t, %1; cvt.u32.u64 %0, t; }" : "=r"(a) : "l"(p));
    return a;
}
__device__ __forceinline__ void mma16816(float* c, const uint32_t* a, uint32_t b0, uint32_t b1) {
    asm volatile(
        "mma.sync.aligned.m16n8k16.row.col.f32.bf16.bf16.f32 "
        "{%0,%1,%2,%3}, {%4,%5,%6,%7}, {%8,%9}, {%0,%1,%2,%3};"
        : "+f"(c[0]), "+f"(c[1]), "+f"(c[2]), "+f"(c[3])
        : "r"(a[0]), "r"(a[1]), "r"(a[2]), "r"(a[3]), "r"(b0), "r"(b1));
}
__device__ __forceinline__ void ldsm_x4(uint32_t* r, uint32_t addr) {
    asm volatile("ldmatrix.sync.aligned.m8n8.x4.shared.b16 {%0,%1,%2,%3}, [%4];"
        : "=r"(r[0]), "=r"(r[1]), "=r"(r[2]), "=r"(r[3]) : "r"(addr));
}
#define CP_ASYNC16(dst, src) asm volatile("cp.async.cg.shared.global [%0], [%1], 16;" :: "r"(dst), "l"(src))
#define CP_COMMIT()  asm volatile("cp.async.commit_group;" ::: "memory")
#define CP_WAIT0()   asm volatile("cp.async.wait_group 0;" ::: "memory")
#define CP_WAIT1()   asm volatile("cp.async.wait_group 1;" ::: "memory")

// SMEM: A0 @0, A1 @32768, B0 @65536, B1 @98304, red @131072
#define SM_A0   0u
#define SM_A1   32768u
#define SM_B0   65536u
#define SM_RED  131072
#define SM_DYN  (131072 + 4096)

// copy a 128x128 bf16 tile (128 rows x 256B) global->smem, chunk-swizzled
__device__ __forceinline__ void cpa_tile(uint32_t dst, const char* __restrict__ src) {
    int tid = threadIdx.x;
#pragma unroll
    for (int i = 0; i < 8; i++) {
        int c = tid + i * 256;
        int r = c >> 4, cc = c & 15;
        uint32_t d = dst + r * 256 + (((uint32_t)(cc ^ (r & 7))) << 4);
        CP_ASYNC16(d, src + r * 256 + cc * 16);
    }
}

// ---------------------------------------------------------------------------
// Prep kernels (normalize + bf16 convert)
// ---------------------------------------------------------------------------
__global__ void prep_ins(const float* __restrict__ v1, const float* __restrict__ v2) {
    int lane = threadIdx.x & 31;
    int gw = (blockIdx.x * blockDim.x + threadIdx.x) >> 5;
    for (int r = gw; r < N_INS; r += 4096) {
        const float* src = (r < B_INS) ? v1 + (size_t)r * DDIM : v2 + (size_t)(r - B_INS) * DDIM;
        float4 x = ((const float4*)src)[lane];
        float ss = x.x * x.x + x.y * x.y + x.z * x.z + x.w * x.w;
#pragma unroll
        for (int o = 16; o; o >>= 1) ss += __shfl_xor_sync(~0u, ss, o);
        float ri = 1.0f / fmaxf(sqrtf(ss), 1e-12f);
        __nv_bfloat162 p0 = __floats2bfloat162_rn(x.x * ri, x.y * ri);
        __nv_bfloat162 p1 = __floats2bfloat162_rn(x.z * ri, x.w * ri);
        ((uint2*)g_I)[(size_t)r * 32 + lane] = make_uint2(*(uint32_t*)&p0, *(uint32_t*)&p1);
    }
}

__global__ void prep_patch(const float* __restrict__ v1p, const float* __restrict__ v2p) {
    __shared__ float sb[2][32][129];
    int tid = threadIdx.x, lane = tid & 31, wid = tid >> 5;
    int j0 = blockIdx.x * 32;
    int b = blockIdx.y;
    const float* srcs[2] = { v1p + (size_t)b * DDIM * 256, v2p + (size_t)b * DDIM * 256 };
#pragma unroll
    for (int s = 0; s < 2; s++) {
        const float* src = srcs[s];
        for (int i = 0; i < 16; i++) {
            int idx = tid + i * 256;
            int k = idx >> 5, jj = idx & 31;
            sb[s][jj][k] = src[(size_t)k * 256 + j0 + jj];
        }
    }
    __syncthreads();
    for (int t = 0; t < 8; t++) {
        int rr = wid * 8 + t;
        int s = rr >> 5, jj = rr & 31;
        float x0 = sb[s][jj][lane * 4 + 0];
        float x1 = sb[s][jj][lane * 4 + 1];
        float x2 = sb[s][jj][lane * 4 + 2];
        float x3 = sb[s][jj][lane * 4 + 3];
        float ss = x0 * x0 + x1 * x1 + x2 * x2 + x3 * x3;
#pragma unroll
        for (int o = 16; o; o >>= 1) ss += __shfl_xor_sync(~0u, ss, o);
        float ri = 1.0f / fmaxf(sqrtf(ss), 1e-12f);
        __nv_bfloat162 p0 = __floats2bfloat162_rn(x0 * ri, x1 * ri);
        __nv_bfloat162 p1 = __floats2bfloat162_rn(x2 * ri, x3 * ri);
        size_t row = (size_t)b * 512 + s * 256 + j0 + jj;
        ((uint2*)g_P)[row * 32 + lane] = make_uint2(*(uint32_t*)&p0, *(uint32_t*)&p1);
    }
}

// ---------------------------------------------------------------------------
// tile decode: given CTA role + list position, return (sel, Bsrc, outRow, outCol, diag)
// ---------------------------------------------------------------------------
struct Role {
    int x;            // instance pair id (ins)
    int b, p;         // patch batch, pair (pat)
    bool ins;
};

__device__ __forceinline__ const char* tile_info(const Role& R, int tt, int& sel,
                                                 float*& outR, float*& outC, bool& diag) {
    int bi, bj;
    if (R.ins) {
        if (tt < 128 - R.x) { sel = 0; bi = R.x; bj = R.x + tt; }
        else                { sel = 1; bi = 127 - R.x; bj = tt - (128 - R.x) + 127 - R.x; }
        outR = g_part + (size_t)(bi * 128 + bj) * 128;
        outC = g_part + (size_t)(bj * 128 + bi) * 128;
        diag = (bi == bj);
        return (const char*)g_I + (size_t)bj * 128 * 256;
    } else {
        if (R.p == 0) { if (tt < 4) { sel = 0; bi = 0; bj = tt; } else { sel = 1; bi = 3; bj = 3; } }
        else          { if (tt < 3) { sel = 0; bi = 1; bj = 1 + tt; } else { sel = 1; bi = 2; bj = 2 + (tt - 3); } }
        outR = g_ppart + (size_t)(R.b * 16 + bi * 4 + bj) * 128;
        outC = g_ppart + (size_t)(R.b * 16 + bj * 4 + bi) * 128;
        diag = (bi == bj);
        return (const char*)g_P + ((size_t)R.b * 512 + (size_t)bj * 128) * 256;
    }
}

// ---------------------------------------------------------------------------
// Main: symmetric upper-tri tiles; row + col partials per tile.
// grid 768: cta<256 instance (x=cta>>2, slot=cta&3, 129 tiles strided by 4),
//           cta>=256 patch ((cta-256)>>1 = batch, &1 = pair, 5 tiles).
// ---------------------------------------------------------------------------
__global__ void __launch_bounds__(256, 1) k_main() {
    extern __shared__ char sm[];
    uint32_t sbu = smem_u32(sm);
    float* red_row = (float*)(sm + SM_RED);          // 256
    float* red_col = (float*)(sm + SM_RED + 1024);   // 512

    int tid = threadIdx.x, lane = tid & 31, wid = tid >> 5;
    int g = lane >> 2, t = lane & 3;
    int l7 = lane & 7, l15 = lane & 15, hi = lane >> 4;
    int warpM = wid >> 1, warpN = wid & 1;
    int woff = warpM * 32, noff = warpN * 64;

    Role R;
    int cta = blockIdx.x;
    int t0, step, L;
    const char *A0src, *A1src;
    if (cta < 256) {
        R.ins = true; R.x = cta >> 2; R.b = 0; R.p = 0;
        t0 = cta & 3; step = 4; L = 129;
        A0src = (const char*)g_I + (size_t)R.x * 128 * 256;
        A1src = (const char*)g_I + (size_t)(127 - R.x) * 128 * 256;
    } else {
        int pc = cta - 256;
        R.ins = false; R.b = pc >> 1; R.p = pc & 1; R.x = 0;
        t0 = 0; step = 1; L = 5;
        int a0b = R.p ? 1 : 0, a1b = R.p ? 2 : 3;
        A0src = (const char*)g_P + ((size_t)R.b * 512 + a0b * 128) * 256;
        A1src = (const char*)g_P + ((size_t)R.b * 512 + a1b * 128) * 256;
    }

    // prologue: A0 + A1 + first B in group 0; second B in group 1
    int sel; float *outR, *outC; bool diag;
    cpa_tile(sbu + SM_A0, A0src);
    cpa_tile(sbu + SM_A1, A1src);
    cpa_tile(sbu + SM_B0, tile_info(R, t0, sel, outR, outC, diag));
    CP_COMMIT();
    if (t0 + step < L) {
        cpa_tile(sbu + SM_B0 + 32768u, tile_info(R, t0 + step, sel, outR, outC, diag));
        CP_COMMIT();
    }

    uint32_t aF[8][2][4];     // resident A fragments for current sel
    int cursel = -1;

    int it = 0;
    for (int tt = t0; tt < L; tt += step, it++) {
        if (tt + step < L) CP_WAIT1(); else CP_WAIT0();
        __syncthreads();

        const char* dummy = tile_info(R, tt, sel, outR, outC, diag);
        (void)dummy;

        if (sel != cursel) {
            cursel = sel;
            uint32_t abase = sbu + (sel ? SM_A1 : SM_A0) + (uint32_t)(woff + l15) * 256;
#pragma unroll
            for (int ks = 0; ks < 8; ks++) {
                uint32_t coff = (uint32_t)((((ks << 1) | hi) ^ l7) << 4);
                ldsm_x4(aF[ks][0], abase + coff);
                ldsm_x4(aF[ks][1], abase + 16 * 256 + coff);
            }
        }

        uint32_t bbuf = sbu + SM_B0 + ((uint32_t)(it & 1) << 15);
        uint32_t bRow = bbuf + (uint32_t)(noff + l15) * 256;

        float acc[2][8][4];
#pragma unroll
        for (int mi = 0; mi < 2; mi++)
#pragma unroll
            for (int ni = 0; ni < 8; ni++)
#pragma unroll
                for (int q = 0; q < 4; q++) acc[mi][ni][q] = 0.f;

#pragma unroll
        for (int ks = 0; ks < 8; ks++) {
            uint32_t coff = (uint32_t)((((ks << 1) | hi) ^ l7) << 4);
            uint32_t b[4][4];
#pragma unroll
            for (int nj = 0; nj < 4; nj++)
                ldsm_x4(b[nj], bRow + nj * 16 * 256 + coff);
#pragma unroll
            for (int nj = 0; nj < 4; nj++) {
                mma16816(acc[0][nj * 2 + 0], aF[ks][0], b[nj][0], b[nj][2]);
                mma16816(acc[0][nj * 2 + 1], aF[ks][0], b[nj][1], b[nj][3]);
                mma16816(acc[1][nj * 2 + 0], aF[ks][1], b[nj][0], b[nj][2]);
                mma16816(acc[1][nj * 2 + 1], aF[ks][1], b[nj][1], b[nj][3]);
            }
        }

        __syncthreads();   // B buffer free
        if (tt + 2 * step < L) {
            int s2; float *r2, *c2; bool d2;
            cpa_tile(bbuf, tile_info(R, tt + 2 * step, s2, r2, c2, d2));
            CP_COMMIT();
        }

        // epilogue: e = exp(10*d - 10); accumulate row sums and col sums
        float rsum[2][2] = {{0.f, 0.f}, {0.f, 0.f}};
        float csum[16];
#pragma unroll
        for (int i = 0; i < 16; i++) csum[i] = 0.f;

#pragma unroll
        for (int mi = 0; mi < 2; mi++)
#pragma unroll
            for (int ni = 0; ni < 8; ni++)
#pragma unroll
                for (int q = 0; q < 4; q++) {
                    float e = ex2f(fmaf(acc[mi][ni][q], L2E10, -L2E10));
                    rsum[mi][q >> 1] += e;
                    csum[ni * 2 + (q & 1)] += e;
                }

        // row reduce over t lanes
#pragma unroll
        for (int mi = 0; mi < 2; mi++)
#pragma unroll
            for (int h = 0; h < 2; h++) {
                float v = rsum[mi][h];
                v += __shfl_xor_sync(~0u, v, 1);
                v += __shfl_xor_sync(~0u, v, 2);
                if (t == 0) red_row[warpN * 128 + woff + mi * 16 + h * 8 + g] = v;
            }
        // col reduce over g lanes
#pragma unroll
        for (int i = 0; i < 16; i++) {
            float v = csum[i];
            v += __shfl_xor_sync(~0u, v, 4);
            v += __shfl_xor_sync(~0u, v, 8);
            v += __shfl_xor_sync(~0u, v, 16);
            if (g == 0) red_col[warpM * 128 + noff + (i >> 1) * 8 + t * 2 + (i & 1)] = v;
        }
        __syncthreads();
        if (tid < 128) {
            outR[tid] = red_row[tid] + red_row[128 + tid];
        } else if (!diag) {
            int c = tid - 128;
            outC[c] = red_col[c] + red_col[128 + c] + red_col[256 + c] + red_col[384 + c];
        }
    }
}

// ---------------------------------------------------------------------------
// Fixup + row loss: loss_r = 10 + log(S_r - exp(10*diag-10)) - 10*pos
// ---------------------------------------------------------------------------
__device__ __forceinline__ void dots_row(const uint2* a, const uint2* b, int lane,
                                         float& pos, float& dia) {
    uint2 ua = a[lane], ub = b[lane];
    __nv_bfloat162 a0 = *(__nv_bfloat162*)&ua.x, a1 = *(__nv_bfloat162*)&ua.y;
    __nv_bfloat162 b0 = *(__nv_bfloat162*)&ub.x, b1 = *(__nv_bfloat162*)&ub.y;
    float ax0 = __bfloat162float(a0.x), ax1 = __bfloat162float(a0.y);
    float ax2 = __bfloat162float(a1.x), ax3 = __bfloat162float(a1.y);
    float bx0 = __bfloat162float(b0.x), bx1 = __bfloat162float(b0.y);
    float bx2 = __bfloat162float(b1.x), bx3 = __bfloat162float(b1.y);
    pos = ax0 * bx0 + ax1 * bx1 + ax2 * bx2 + ax3 * bx3;
    dia = ax0 * ax0 + ax1 * ax1 + ax2 * ax2 + ax3 * ax3;
}

__global__ void fin_ins() {
    __shared__ float rs[256];
    int tid = threadIdx.x, lane = tid & 31;
    int gw = (blockIdx.x * 256 + tid) >> 5;
    float acc = 0.0f;
    for (int r = gw; r < N_INS; r += 4096) {
        int bi = r >> 7, m = r & 127;
        const float* pp = g_part + (size_t)bi * 16384 + m;
        float Sp = 0.0f;
#pragma unroll
        for (int bj = lane; bj < 128; bj += 32) Sp += pp[(size_t)bj * 128];
        float pos, dia;
        dots_row(((const uint2*)g_I) + (size_t)r * 32,
                 ((const uint2*)g_I) + (size_t)(r ^ B_INS) * 32, lane, pos, dia);
#pragma unroll
        for (int o = 16; o; o >>= 1) {
            Sp  += __shfl_xor_sync(~0u, Sp, o);
            pos += __shfl_xor_sync(~0u, pos, o);
            dia += __shfl_xor_sync(~0u, dia, o);
        }
        if (lane == 0) {
            float S = Sp - ex2f(fmaf(dia, L2E10, -L2E10));
            acc += 10.0f + logf(S) - 10.0f * pos;
        }
    }
    rs[tid] = acc;
    __syncthreads();
    for (int s = 128; s; s >>= 1) { if (tid < s) rs[tid] += rs[tid + s]; __syncthreads(); }
    if (tid == 0) g_fin1[blockIdx.x] = rs[0];
}

__global__ void fin_patch(const int* __restrict__ c1, const int* __restrict__ c2) {
    __shared__ float rs[256];
    int tid = threadIdx.x, lane = tid & 31;
    int gw = (blockIdx.x * 256 + tid) >> 5;
    float acc = 0.0f;
    for (int r = gw; r < NPROW; r += 8192) {
        int b = r >> 9, rl = r & 511;
        int c = (rl < 256) ? c1[b * 256 + rl] : c2[b * 256 + rl - 256];
        if (c == 0) continue;
        int bi = rl >> 7, m = rl & 127;
        float Sp = (lane < 4) ? g_ppart[(size_t)(b * 16 + bi * 4 + lane) * 128 + m] : 0.0f;
        float pos, dia;
        dots_row(((const uint2*)g_P) + (size_t)r * 32,
                 ((const uint2*)g_P) + (size_t)(r ^ 256) * 32, lane, pos, dia);
#pragma unroll
        for (int o = 16; o; o >>= 1) {
            Sp  += __shfl_xor_sync(~0u, Sp, o);
            pos += __shfl_xor_sync(~0u, pos, o);
            dia += __shfl_xor_sync(~0u, dia, o);
        }
        if (lane == 0) {
            float S = Sp - ex2f(fmaf(dia, L2E10, -L2E10));
            acc += 10.0f + logf(S) - 10.0f * pos;
        }
    }
    rs[tid] = acc;
    __syncthreads();
    for (int s = 128; s; s >>= 1) { if (tid < s) rs[tid] += rs[tid + s]; __syncthreads(); }
    if (tid == 0) g_fin2[blockIdx.x] = rs[0];
}

__global__ void k_combine(const int* __restrict__ c1, const int* __restrict__ c2,
                          float* __restrict__ out) {
    __shared__ float rs[256];
    __shared__ int ri[256];
    int tid = threadIdx.x;
    float a = 0.0f, p = 0.0f;
    int cnt = 0;
    for (int i = tid; i < 512; i += 256) a += g_fin1[i];
    for (int i = tid; i < 1024; i += 256) p += g_fin2[i];
    for (int i = tid; i < 65536; i += 256) cnt += (c1[i] != 0) + (c2[i] != 0);
    rs[tid] = a; ri[tid] = cnt;
    __syncthreads();
    for (int s = 128; s; s >>= 1) {
        if (tid < s) { rs[tid] += rs[tid + s]; ri[tid] += ri[tid + s]; }
        __syncthreads();
    }
    float ins_sum = rs[0];
    int nvalid = ri[0];
    __syncthreads();
    rs[tid] = p;
    __syncthreads();
    for (int s = 128; s; s >>= 1) { if (tid < s) rs[tid] += rs[tid + s]; __syncthreads(); }
    if (tid == 0)
        out[0] = ins_sum / (float)N_INS + rs[0] / (float)nvalid;
}

// ---------------------------------------------------------------------------
extern "C" void kernel_launch(void* const* d_in, const int* in_sizes, int n_in,
                              void* d_out, int out_size) {
    const float* v1  = (const float*)d_in[0];
    const float* v2  = (const float*)d_in[1];
    const float* v1p = (const float*)d_in[2];
    const float* v2p = (const float*)d_in[3];
    const int*   c1  = (const int*)d_in[4];
    const int*   c2  = (const int*)d_in[5];
    float* out = (float*)d_out;

    cudaFuncSetAttribute(k_main, cudaFuncAttributeMaxDynamicSharedMemorySize, SM_DYN);

    prep_ins<<<512, 256>>>(v1, v2);
    prep_patch<<<dim3(8, 256), 256>>>(v1p, v2p);
    k_main<<<768, 256, SM_DYN>>>();
    fin_ins<<<512, 256>>>();
    fin_patch<<<1024, 256>>>(c1, c2);
    k_combine<<<1, 256>>>(c1, c2, out);
}

// round 7
// speedup vs baseline: 10.2799x; 1.1076x over previous
#include <cuda_runtime.h>
#include <cuda_bf16.h>
#include <cstdint>
#include <math.h>

// ---------------------------------------------------------------------------
// MultiLevelSimCLR, symmetric tiles, occupancy-2 HMMA version.
// One A block per CTA; partial row/col sums written directly to global slots.
// ---------------------------------------------------------------------------

#define B_INS   8192
#define N_INS   16384
#define DDIM    128
#define NPROW   131072
#define L2E10   14.4269504088896340f

// ---- static device scratch ----
__device__ __align__(16) uint32_t g_I[N_INS * 64];       // bf16 instance embs [r][128]
__device__ __align__(16) uint32_t g_P[NPROW * 64];       // bf16 patch embs
__device__ float g_part[128 * 128 * 4 * 128];            // [bi][bj][slot][m]  33.5 MB
__device__ float g_pp[256 * 16 * 4 * 128];               // [b][i*4+j][slot][m] 8.4 MB
__device__ float g_fin1[128];
__device__ float g_fin2[1024];

__device__ __forceinline__ float ex2f(float x) {
    float y; asm("ex2.approx.f32 %0, %1;" : "=f"(y) : "f"(x)); return y;
}
__device__ __forceinline__ uint32_t smem_u32(const void* p) {
    uint32_t a;
    asm("{ .reg .u64 t; cvta.to.shared.u64 t, %1; cvt.u32.u64 %0, t; }" : "=r"(a) : "l"(p));
    return a;
}
__device__ __forceinline__ void mma16816(float* c, const uint32_t* a, uint32_t b0, uint32_t b1) {
    asm volatile(
        "mma.sync.aligned.m16n8k16.row.col.f32.bf16.bf16.f32 "
        "{%0,%1,%2,%3}, {%4,%5,%6,%7}, {%8,%9}, {%0,%1,%2,%3};"
        : "+f"(c[0]), "+f"(c[1]), "+f"(c[2]), "+f"(c[3])
        : "r"(a[0]), "r"(a[1]), "r"(a[2]), "r"(a[3]), "r"(b0), "r"(b1));
}
__device__ __forceinline__ void ldsm_x4(uint32_t* r, uint32_t addr) {
    asm volatile("ldmatrix.sync.aligned.m8n8.x4.shared.b16 {%0,%1,%2,%3}, [%4];"
        : "=r"(r[0]), "=r"(r[1]), "=r"(r[2]), "=r"(r[3]) : "r"(addr));
}
#define CP_ASYNC16(dst, src) asm volatile("cp.async.cg.shared.global [%0], [%1], 16;" :: "r"(dst), "l"(src))
#define CP_COMMIT()  asm volatile("cp.async.commit_group;" ::: "memory")
#define CP_WAIT0()   asm volatile("cp.async.wait_group 0;" ::: "memory")
#define CP_WAIT1()   asm volatile("cp.async.wait_group 1;" ::: "memory")

// SMEM: A @0 (32KB), B0 @32768, B1 @65536. Total exactly 96KB.
#define SM_A    0u
#define SM_B0   32768u
#define SM_DYN  98304

// copy a 128x128 bf16 tile (128 rows x 256B) global->smem, chunk-swizzled
__device__ __forceinline__ void cpa_tile(uint32_t dst, const char* __restrict__ src) {
    int tid = threadIdx.x;
#pragma unroll
    for (int i = 0; i < 8; i++) {
        int c = tid + i * 256;
        int r = c >> 4, cc = c & 15;
        uint32_t d = dst + r * 256 + (((uint32_t)(cc ^ (r & 7))) << 4);
        CP_ASYNC16(d, src + r * 256 + cc * 16);
    }
}

// ---------------------------------------------------------------------------
// Prep kernels
// ---------------------------------------------------------------------------
__global__ void prep_ins(const float* __restrict__ v1, const float* __restrict__ v2) {
    int lane = threadIdx.x & 31;
    int gw = (blockIdx.x * blockDim.x + threadIdx.x) >> 5;
    for (int r = gw; r < N_INS; r += 4096) {
        const float* src = (r < B_INS) ? v1 + (size_t)r * DDIM : v2 + (size_t)(r - B_INS) * DDIM;
        float4 x = ((const float4*)src)[lane];
        float ss = x.x * x.x + x.y * x.y + x.z * x.z + x.w * x.w;
#pragma unroll
        for (int o = 16; o; o >>= 1) ss += __shfl_xor_sync(~0u, ss, o);
        float ri = 1.0f / fmaxf(sqrtf(ss), 1e-12f);
        __nv_bfloat162 p0 = __floats2bfloat162_rn(x.x * ri, x.y * ri);
        __nv_bfloat162 p1 = __floats2bfloat162_rn(x.z * ri, x.w * ri);
        ((uint2*)g_I)[(size_t)r * 32 + lane] = make_uint2(*(uint32_t*)&p0, *(uint32_t*)&p1);
    }
}

__global__ void prep_patch(const float* __restrict__ v1p, const float* __restrict__ v2p) {
    __shared__ float sb[2][32][129];
    int tid = threadIdx.x, lane = tid & 31, wid = tid >> 5;
    int j0 = blockIdx.x * 32;
    int b = blockIdx.y;
    const float* srcs[2] = { v1p + (size_t)b * DDIM * 256, v2p + (size_t)b * DDIM * 256 };
#pragma unroll
    for (int s = 0; s < 2; s++) {
        const float* src = srcs[s];
        for (int i = 0; i < 16; i++) {
            int idx = tid + i * 256;
            int k = idx >> 5, jj = idx & 31;
            sb[s][jj][k] = src[(size_t)k * 256 + j0 + jj];
        }
    }
    __syncthreads();
    for (int t = 0; t < 8; t++) {
        int rr = wid * 8 + t;
        int s = rr >> 5, jj = rr & 31;
        float x0 = sb[s][jj][lane * 4 + 0];
        float x1 = sb[s][jj][lane * 4 + 1];
        float x2 = sb[s][jj][lane * 4 + 2];
        float x3 = sb[s][jj][lane * 4 + 3];
        float ss = x0 * x0 + x1 * x1 + x2 * x2 + x3 * x3;
#pragma unroll
        for (int o = 16; o; o >>= 1) ss += __shfl_xor_sync(~0u, ss, o);
        float ri = 1.0f / fmaxf(sqrtf(ss), 1e-12f);
        __nv_bfloat162 p0 = __floats2bfloat162_rn(x0 * ri, x1 * ri);
        __nv_bfloat162 p1 = __floats2bfloat162_rn(x2 * ri, x3 * ri);
        size_t row = (size_t)b * 512 + s * 256 + j0 + jj;
        ((uint2*)g_P)[row * 32 + lane] = make_uint2(*(uint32_t*)&p0, *(uint32_t*)&p1);
    }
}

// ---------------------------------------------------------------------------
// Main kernel. grid 1536:
//   bid<512:  instance, row block x = bid>>2, slot = bid&3, tiles bj = x+slot+4i
//   bid>=512: patch, pc=bid-512, b=pc>>2, bi=pc&3, tiles bj = bi+i (L=4-bi)
// Each tile writes row partials [pairR][warpN][m] and (non-diag) col partials
// [pairC][warpM][m] directly to global; fixup kernels sum slots.
// ---------------------------------------------------------------------------
__global__ void __launch_bounds__(256, 2) k_main() {
    extern __shared__ char sm[];
    uint32_t sbu = smem_u32(sm);

    int tid = threadIdx.x, lane = tid & 31, wid = tid >> 5;
    int g = lane >> 2, t = lane & 3;
    int l7 = lane & 7, l15 = lane & 15, hi = lane >> 4;
    int warpM = wid >> 1, warpN = wid & 1;
    int woff = warpM * 32, noff = warpN * 64;

    int bid = blockIdx.x;
    const char* Asrc;
    const char* Bembs;       // row-block base table (block stride 32768 B)
    float* partBase;         // partial array base for this family
    int pairStrideRow;       // pair index = rowsel*rowStride + colsel
    int rowIdx;              // this CTA's A block index within family
    int bj0, bjstep, L;

    if (bid < 512) {
        int x = bid >> 2, slot = bid & 3;
        rowIdx = x;
        bj0 = x + slot; bjstep = 4;
        L = (bj0 <= 127) ? ((127 - bj0) >> 2) + 1 : 0;
        Asrc = (const char*)g_I + (size_t)x * 32768;
        Bembs = (const char*)g_I;
        partBase = g_part;
        pairStrideRow = 128;
    } else {
        int pc = bid - 512;
        int b = pc >> 2, bi = pc & 3;
        rowIdx = bi;
        bj0 = bi; bjstep = 1;
        L = 4 - bi;
        Asrc = (const char*)g_P + ((size_t)b * 512 + (size_t)bi * 128) * 256;
        Bembs = (const char*)g_P + (size_t)b * 512 * 256;
        partBase = g_pp + (size_t)b * 16 * 4 * 128;
        pairStrideRow = 4;
    }
    if (L == 0) return;

    // prologue
    cpa_tile(sbu + SM_A, Asrc);
    cpa_tile(sbu + SM_B0, Bembs + (size_t)bj0 * 32768);
    CP_COMMIT();
    if (L > 1) {
        cpa_tile(sbu + SM_B0 + 32768u, Bembs + (size_t)(bj0 + bjstep) * 32768);
        CP_COMMIT();
    }

    uint32_t aAddr0 = sbu + SM_A + (uint32_t)(woff + l15) * 256;
    uint32_t aAddr1 = aAddr0 + 16 * 256;

    for (int i = 0; i < L; i++) {
        int bj = bj0 + i * bjstep;
        bool diag = (bj == rowIdx);

        if (i + 1 < L) CP_WAIT1(); else CP_WAIT0();
        __syncthreads();

        uint32_t bbuf = sbu + SM_B0 + ((uint32_t)(i & 1) << 15);
        uint32_t bRow = bbuf + (uint32_t)(noff + l15) * 256;

        float acc[2][8][4];
#pragma unroll
        for (int mi = 0; mi < 2; mi++)
#pragma unroll
            for (int ni = 0; ni < 8; ni++)
#pragma unroll
                for (int q = 0; q < 4; q++) acc[mi][ni][q] = 0.f;

#pragma unroll
        for (int ks = 0; ks < 8; ks++) {
            uint32_t coff = (uint32_t)((((ks << 1) | hi) ^ l7) << 4);
            uint32_t a[2][4];
            ldsm_x4(a[0], aAddr0 + coff);
            ldsm_x4(a[1], aAddr1 + coff);
            uint32_t b[4][4];
#pragma unroll
            for (int nj = 0; nj < 4; nj++)
                ldsm_x4(b[nj], bRow + nj * 16 * 256 + coff);
#pragma unroll
            for (int nj = 0; nj < 4; nj++) {
                mma16816(acc[0][nj * 2 + 0], a[0], b[nj][0], b[nj][2]);
                mma16816(acc[0][nj * 2 + 1], a[0], b[nj][1], b[nj][3]);
                mma16816(acc[1][nj * 2 + 0], a[1], b[nj][0], b[nj][2]);
                mma16816(acc[1][nj * 2 + 1], a[1], b[nj][1], b[nj][3]);
            }
        }

        __syncthreads();   // B buffer consumed
        if (i + 2 < L) {
            cpa_tile(bbuf, Bembs + (size_t)(bj + 2 * bjstep) * 32768);
            CP_COMMIT();
        }

        // epilogue: e = exp(10d - 10); row sums and column sums
        float rsum[2][2] = {{0.f, 0.f}, {0.f, 0.f}};
        float csum[16];
#pragma unroll
        for (int k2 = 0; k2 < 16; k2++) csum[k2] = 0.f;

#pragma unroll
        for (int mi = 0; mi < 2; mi++)
#pragma unroll
            for (int ni = 0; ni < 8; ni++)
#pragma unroll
                for (int q = 0; q < 4; q++) {
                    float e = ex2f(fmaf(acc[mi][ni][q], L2E10, -L2E10));
                    rsum[mi][q >> 1] += e;
                    csum[ni * 2 + (q & 1)] += e;
                }

        float* outR = partBase + (size_t)(rowIdx * pairStrideRow + bj) * 512;
        float* outC = partBase + (size_t)(bj * pairStrideRow + rowIdx) * 512;

        // row partials: reduce over t lanes, slot = warpN
#pragma unroll
        for (int mi = 0; mi < 2; mi++)
#pragma unroll
            for (int h = 0; h < 2; h++) {
                float v = rsum[mi][h];
                v += __shfl_xor_sync(~0u, v, 1);
                v += __shfl_xor_sync(~0u, v, 2);
                if (t == 0) outR[warpN * 128 + woff + mi * 16 + h * 8 + g] = v;
            }
        // col partials: reduce over g lanes, slot = warpM
        if (!diag) {
#pragma unroll
            for (int k2 = 0; k2 < 16; k2++) {
                float v = csum[k2];
                v += __shfl_xor_sync(~0u, v, 4);
                v += __shfl_xor_sync(~0u, v, 8);
                v += __shfl_xor_sync(~0u, v, 16);
                if (g == 0) outC[warpM * 128 + noff + (k2 >> 1) * 8 + t * 2 + (k2 & 1)] = v;
            }
        }
    }
}

// ---------------------------------------------------------------------------
// Fixups. part layout per family: [bi][j][slot][m].
// For row-block bi: S[m] = sum_j ( slots 0,1  +  (j<bi ? slots 2,3 : 0) ).
// ---------------------------------------------------------------------------
__device__ __forceinline__ void dots_row(const uint2* a, const uint2* b, int lane,
                                         float& pos, float& dia) {
    uint2 ua = a[lane], ub = b[lane];
    __nv_bfloat162 a0 = *(__nv_bfloat162*)&ua.x, a1 = *(__nv_bfloat162*)&ua.y;
    __nv_bfloat162 b0 = *(__nv_bfloat162*)&ub.x, b1 = *(__nv_bfloat162*)&ub.y;
    float ax0 = __bfloat162float(a0.x), ax1 = __bfloat162float(a0.y);
    float ax2 = __bfloat162float(a1.x), ax3 = __bfloat162float(a1.y);
    float bx0 = __bfloat162float(b0.x), bx1 = __bfloat162float(b0.y);
    float bx2 = __bfloat162float(b1.x), bx3 = __bfloat162float(b1.y);
    pos = ax0 * bx0 + ax1 * bx1 + ax2 * bx2 + ax3 * bx3;
    dia = ax0 * ax0 + ax1 * ax1 + ax2 * ax2 + ax3 * ax3;
#pragma unroll
    for (int o = 16; o; o >>= 1) {
        pos += __shfl_xor_sync(~0u, pos, o);
        dia += __shfl_xor_sync(~0u, dia, o);
    }
}

__global__ void fin_ins() {
    __shared__ float S[128];
    __shared__ float S2[256];
    __shared__ float rs[256];
    int bi = blockIdx.x;
    int tid = threadIdx.x;
    int m = tid & 127, jh = tid >> 7;

    const float* base = g_part + (size_t)bi * 128 * 512 + m;
    float s = 0.0f;
    for (int j = jh * 64; j < jh * 64 + 64; j++) {
        const float* p = base + (size_t)j * 512;
        s += p[0] + p[128];
        if (j < bi) s += p[256] + p[384];
    }
    S2[tid] = s;
    __syncthreads();
    if (tid < 128) S[tid] = S2[tid] + S2[tid + 128];
    __syncthreads();

    int lane = tid & 31, wid = tid >> 5;
    float acc = 0.0f;
#pragma unroll 4
    for (int ii = 0; ii < 16; ii++) {
        int mm = wid * 16 + ii;
        int r = bi * 128 + mm;
        float pos, dia;
        dots_row(((const uint2*)g_I) + (size_t)r * 32,
                 ((const uint2*)g_I) + (size_t)(r ^ B_INS) * 32, lane, pos, dia);
        if (lane == 0) {
            float Sv = S[mm] - ex2f(fmaf(dia, L2E10, -L2E10));
            acc += 10.0f + logf(Sv) - 10.0f * pos;
        }
    }
    rs[tid] = acc;
    __syncthreads();
    for (int s2 = 128; s2; s2 >>= 1) { if (tid < s2) rs[tid] += rs[tid + s2]; __syncthreads(); }
    if (tid == 0) g_fin1[bi] = rs[0];
}

__global__ void fin_patch(const int* __restrict__ c1, const int* __restrict__ c2) {
    __shared__ float S[128];
    __shared__ float S2[256];
    __shared__ float rs[256];
    int pc = blockIdx.x;
    int b = pc >> 2, bi = pc & 3;
    int tid = threadIdx.x;
    int m = tid & 127, jh = tid >> 7;

    const float* base = g_pp + ((size_t)b * 16 + bi * 4) * 512 + m;
    float s = 0.0f;
    for (int j = jh * 2; j < jh * 2 + 2; j++) {
        const float* p = base + (size_t)j * 512;
        s += p[0] + p[128];
        if (j < bi) s += p[256] + p[384];
    }
    S2[tid] = s;
    __syncthreads();
    if (tid < 128) S[tid] = S2[tid] + S2[tid + 128];
    __syncthreads();

    int lane = tid & 31, wid = tid >> 5;
    float acc = 0.0f;
#pragma unroll 4
    for (int ii = 0; ii < 16; ii++) {
        int mm = wid * 16 + ii;
        int rl = bi * 128 + mm;
        int r = b * 512 + rl;
        int c = (rl < 256) ? c1[b * 256 + rl] : c2[b * 256 + rl - 256];
        float pos, dia;
        dots_row(((const uint2*)g_P) + (size_t)r * 32,
                 ((const uint2*)g_P) + (size_t)(r ^ 256) * 32, lane, pos, dia);
        if (lane == 0 && c != 0) {
            float Sv = S[mm] - ex2f(fmaf(dia, L2E10, -L2E10));
            acc += 10.0f + logf(Sv) - 10.0f * pos;
        }
    }
    rs[tid] = acc;
    __syncthreads();
    for (int s2 = 128; s2; s2 >>= 1) { if (tid < s2) rs[tid] += rs[tid + s2]; __syncthreads(); }
    if (tid == 0) g_fin2[pc] = rs[0];
}

__global__ void k_combine(const int* __restrict__ c1, const int* __restrict__ c2,
                          float* __restrict__ out) {
    __shared__ float rs[256];
    __shared__ int ri[256];
    int tid = threadIdx.x;
    float a = 0.0f, p = 0.0f;
    int cnt = 0;
    if (tid < 128) a = g_fin1[tid];
    for (int i = tid; i < 1024; i += 256) p += g_fin2[i];
    for (int i = tid; i < 65536; i += 256) cnt += (c1[i] != 0) + (c2[i] != 0);
    rs[tid] = a; ri[tid] = cnt;
    __syncthreads();
    for (int s = 128; s; s >>= 1) {
        if (tid < s) { rs[tid] += rs[tid + s]; ri[tid] += ri[tid + s]; }
        __syncthreads();
    }
    float ins_sum = rs[0];
    int nvalid = ri[0];
    __syncthreads();
    rs[tid] = p;
    __syncthreads();
    for (int s = 128; s; s >>= 1) { if (tid < s) rs[tid] += rs[tid + s]; __syncthreads(); }
    if (tid == 0)
        out[0] = ins_sum / (float)N_INS + rs[0] / (float)nvalid;
}

// ---------------------------------------------------------------------------
extern "C" void kernel_launch(void* const* d_in, const int* in_sizes, int n_in,
                              void* d_out, int out_size) {
    const float* v1  = (const float*)d_in[0];
    const float* v2  = (const float*)d_in[1];
    const float* v1p = (const float*)d_in[2];
    const float* v2p = (const float*)d_in[3];
    const int*   c1  = (const int*)d_in[4];
    const int*   c2  = (const int*)d_in[5];
    float* out = (float*)d_out;

    cudaFuncSetAttribute(k_main, cudaFuncAttributeMaxDynamicSharedMemorySize, SM_DYN);

    prep_ins<<<512, 256>>>(v1, v2);
    prep_patch<<<dim3(8, 256), 256>>>(v1p, v2p);
    k_main<<<1536, 256, SM_DYN>>>();
    fin_ins<<<128, 256>>>();
    fin_patch<<<1024, 256>>>(c1, c2);
    k_combine<<<1, 256>>>(c1, c2, out);
}